// round 7
// baseline (speedup 1.0000x reference)
#include <cuda_runtime.h>
#include <cuda_fp16.h>
#include <cstdint>

#define NH 4
#define KD 32
#define LSEQ 4096
#define NT 32
#define LOG2E 1.4426950408889634f

// Scratch (allocation-free rule: __device__ globals)
__device__ __half g_Q[2 * NH * LSEQ * KD];  // f16 q
__device__ __half g_K[2 * NH * LSEQ * KD];  // f16 k * scale * log2e
__device__ __half g_V[2 * NH * LSEQ * KD];  // f16 v

// ---------------------------------------------------------------------------
// helpers
// ---------------------------------------------------------------------------
__device__ __forceinline__ uint32_t s2u(const void* p) {
    uint32_t a;
    asm("{ .reg .u64 t; cvta.to.shared.u64 t, %1; cvt.u32.u64 %0, t; }" : "=r"(a) : "l"(p));
    return a;
}
__device__ __forceinline__ float ex2f(float x) {
    float y;
    asm("ex2.approx.f32 %0, %1;" : "=f"(y) : "f"(x));
    return y;
}
__device__ __forceinline__ uint32_t pkh2(float lo, float hi) {
    uint32_t d;
    asm("cvt.rn.f16x2.f32 %0, %1, %2;" : "=r"(d) : "f"(hi), "f"(lo));
    return d;
}
#define CPA(dst, src) asm volatile("cp.async.cg.shared.global [%0], [%1], 16;" ::"r"(dst), "l"(src))
#define CPC() asm volatile("cp.async.commit_group;" ::: "memory")
#define CPW0() asm volatile("cp.async.wait_group 0;" ::: "memory")

__device__ __forceinline__ void mma_f16(float* c, const uint32_t* a, uint32_t b0, uint32_t b1) {
    asm volatile(
        "mma.sync.aligned.m16n8k16.row.col.f32.f16.f16.f32 "
        "{%0,%1,%2,%3}, {%4,%5,%6,%7}, {%8,%9}, {%0,%1,%2,%3};"
        : "+f"(c[0]), "+f"(c[1]), "+f"(c[2]), "+f"(c[3])
        : "r"(a[0]), "r"(a[1]), "r"(a[2]), "r"(a[3]), "r"(b0), "r"(b1));
}
__device__ __forceinline__ void ldsm4(uint32_t* r, uint32_t addr) {
    asm volatile("ldmatrix.sync.aligned.m8n8.x4.shared.b16 {%0,%1,%2,%3}, [%4];"
                 : "=r"(r[0]), "=r"(r[1]), "=r"(r[2]), "=r"(r[3]) : "r"(addr));
}
__device__ __forceinline__ void ldsm4t(uint32_t* r, uint32_t addr) {
    asm volatile("ldmatrix.sync.aligned.m8n8.x4.trans.shared.b16 {%0,%1,%2,%3}, [%4];"
                 : "=r"(r[0]), "=r"(r[1]), "=r"(r[2]), "=r"(r[3]) : "r"(addr));
}

// ---------------------------------------------------------------------------
// QKV projection: fp32 GEMM; outputs Q/V (f16), K (f16, *scale*log2e)
// ---------------------------------------------------------------------------
__global__ __launch_bounds__(256) void qkv_kernel(const float* __restrict__ x,
                                                  const float* __restrict__ w) {
    __shared__ float As[64][36];
    __shared__ float Bs[32][128];
    const int n0 = blockIdx.x * 128;
    const int m0 = blockIdx.y * 64;
    const int tid = threadIdx.x;
    const int ty = tid >> 4, tx = tid & 15;

    float acc[4][8];
#pragma unroll
    for (int i = 0; i < 4; i++)
#pragma unroll
        for (int j = 0; j < 8; j++) acc[i][j] = 0.f;

    for (int kb = 0; kb < 4; kb++) {
#pragma unroll
        for (int r8 = 0; r8 < 2; r8++) {
            int f = tid + 256 * r8;
            int r = f >> 3, k4 = f & 7;
            float4 v = *reinterpret_cast<const float4*>(
                &x[(size_t)(m0 + r) * 128 + kb * 32 + 4 * k4]);
            *reinterpret_cast<float4*>(&As[r][4 * k4]) = v;
        }
#pragma unroll
        for (int r8 = 0; r8 < 4; r8++) {
            int f = tid + 256 * r8;
            int kk = f >> 5, c4 = f & 31;
            float4 v = *reinterpret_cast<const float4*>(
                &w[(size_t)(kb * 32 + kk) * 384 + n0 + 4 * c4]);
            *reinterpret_cast<float4*>(&Bs[kk][4 * c4]) = v;
        }
        __syncthreads();
#pragma unroll
        for (int kk = 0; kk < 32; kk++) {
            float a[4], b[8];
#pragma unroll
            for (int i = 0; i < 4; i++) a[i] = As[4 * ty + i][kk];
#pragma unroll
            for (int j = 0; j < 8; j++) b[j] = Bs[kk][tx + 16 * j];
#pragma unroll
            for (int i = 0; i < 4; i++)
#pragma unroll
                for (int j = 0; j < 8; j++) acc[i][j] = fmaf(a[i], b[j], acc[i][j]);
        }
        __syncthreads();
    }

    const float kscale = 0.17677669529663688f * LOG2E;
#pragma unroll
    for (int i = 0; i < 4; i++) {
        int m = m0 + 4 * ty + i;
        int b = m >> 12, l = m & 4095;
#pragma unroll
        for (int j = 0; j < 8; j++) {
            int c = n0 + tx + 16 * j;
            float v = acc[i][j];
            if (c < 128) {
                int n = c >> 5, d = c & 31;
                g_Q[(((size_t)(b * NH + n)) * LSEQ + l) * KD + d] = __float2half_rn(v);
            } else if (c < 256) {
                int cc = c - 128, n = cc >> 5, d = cc & 31;
                g_K[(((size_t)(b * NH + n)) * LSEQ + l) * KD + d] = __float2half_rn(v * kscale);
            } else {
                int cc = c - 256, n = cc >> 5, d = cc & 31;
                g_V[(((size_t)(b * NH + n)) * LSEQ + l) * KD + d] = __float2half_rn(v);
            }
        }
    }
}

// ---------------------------------------------------------------------------
// f16 HMMA flash attention, 256 threads = 8 warps, 64-query tiles, 2 CTAs/SM.
// warp w: rowgroup rw = w&3 (16 query rows), key-half h = w>>2 (64 keys/tile).
// A 64-query tile is exactly one image row: qi = qb, qj = local row index.
// ---------------------------------------------------------------------------
#define SMQ 0
#define SMK0 5120
#define SMK1 15360
#define SMV0 25600
#define SMV1 35840
#define SMBW 46080
#define SMBH 63488
#define SMTOT 80896
// overlays (consumed before K/V buffers first written / after last use)
#define SMPH 5120
#define SMPW 25600
#define SMRED 5120

__global__ __launch_bounds__(256, 2) void attn_kernel(const float* __restrict__ peh,
                                                      const float* __restrict__ pew,
                                                      float* __restrict__ out) {
    extern __shared__ char sm[];
    const uint32_t sb = s2u(sm);
    const int tid = threadIdx.x;
    const int wid = tid >> 5;
    const int lane = tid & 31;
    const int q4 = lane & 3;
    const int rr = lane >> 2;
    const int qb = blockIdx.x;    // image row / query tile, 0..63
    const int bn = blockIdx.y;    // b*NH + head, 0..7
    const int rw = wid & 3;
    const int h = wid >> 2;       // key-half
    const int m0 = rw * 16;

    const __half* Qg = g_Q + ((size_t)bn * LSEQ + (size_t)qb * 64) * KD;
    const __half* Kg = g_K + (size_t)bn * LSEQ * KD;
    const __half* Vg = g_V + (size_t)bn * LSEQ * KD;

    // ---- prologue: Q tile (f16, 80B rows) + pos tables (fp32, 144B rows) ----
    {
        int r = tid >> 2, c = tid & 3;
        if (r < 64) CPA(sb + SMQ + r * 80 + c * 16, Qg + r * 32 + c * 8);
    }
    for (int u = tid; u < 1016; u += 256) {
        int r = u >> 3, c = u & 7;
        CPA(sb + SMPH + r * 144 + c * 16, peh + r * 32 + 4 * c);
        CPA(sb + SMPW + r * 144 + c * 16, pew + r * 32 + 4 * c);
    }
    CPC();
    CPW0();
    __syncthreads();

    // ---- bias precompute (x log2e): BW[q][kj], BH[q][ki]: [64][68] fp32 ----
    {
        int table = tid >> 7;          // 0 -> BW, 1 -> BH
        int rem = tid & 127;
        int qq = rem >> 1, hc = rem & 1;
        const __half2* qrow = reinterpret_cast<const __half2*>(sm + SMQ + qq * 80);
        float2 qv[16];
#pragma unroll
        for (int i = 0; i < 16; i++) qv[i] = __half22float2(qrow[i]);
        const float* tab = reinterpret_cast<const float*>(sm + (table ? SMPH : SMPW));
        int base = table ? (63 - qb) : (63 - qq);
        float* dst = reinterpret_cast<float*>(sm + (table ? SMBH : SMBW)) + qq * 68;
        for (int kc = 32 * hc; kc < 32 * hc + 32; kc++) {
            const float* er = tab + (base + kc) * 36;
            float s = 0.f;
#pragma unroll
            for (int i = 0; i < 8; i++) {
                float4 e = *reinterpret_cast<const float4*>(&er[4 * i]);
                s = fmaf(qv[2 * i].x, e.x, s);
                s = fmaf(qv[2 * i].y, e.y, s);
                s = fmaf(qv[2 * i + 1].x, e.z, s);
                s = fmaf(qv[2 * i + 1].y, e.w, s);
            }
            dst[kc] = s * LOG2E;
        }
    }
    __syncthreads();

    // ---- Q A-fragments (m16k16 x2 chunks), fixed for all tiles ----
    uint32_t aQ[2][4];
#pragma unroll
    for (int kc = 0; kc < 2; kc++)
        ldsm4(aQ[kc], sb + SMQ + (m0 + (lane & 15)) * 80 + kc * 32 + (lane >> 4) * 16);

    // ---- issue K/V tile 0 (128 keys, f16, 80B rows) ----
    {
        int r = tid >> 1, c = tid & 1;
        CPA(sb + SMK0 + r * 80 + c * 32, Kg + r * 32 + c * 16);
        CPA(sb + SMK0 + r * 80 + c * 32 + 16, Kg + r * 32 + c * 16 + 8);
        CPA(sb + SMV0 + r * 80 + c * 32, Vg + r * 32 + c * 16);
        CPA(sb + SMV0 + r * 80 + c * 32 + 16, Vg + r * 32 + c * 16 + 8);
    }
    CPC();

    const float* BWs = reinterpret_cast<const float*>(sm + SMBW);
    const float* BHs = reinterpret_cast<const float*>(sm + SMBH);

    float o[4][4];
#pragma unroll
    for (int i = 0; i < 4; i++)
#pragma unroll
        for (int j = 0; j < 4; j++) o[i][j] = 0.f;
    float l0 = 0.f, l1 = 0.f;

    for (int t = 0; t < NT; t++) {
        CPW0();
        __syncthreads();
        if (t + 1 < NT) {
            const int nb = (t + 1) & 1;
            const __half* Kt = Kg + (size_t)(t + 1) * 128 * KD;
            const __half* Vt = Vg + (size_t)(t + 1) * 128 * KD;
            const uint32_t kdst = sb + (nb ? SMK1 : SMK0);
            const uint32_t vdst = sb + (nb ? SMV1 : SMV0);
            int r = tid >> 1, c = tid & 1;
            CPA(kdst + r * 80 + c * 32, Kt + r * 32 + c * 16);
            CPA(kdst + r * 80 + c * 32 + 16, Kt + r * 32 + c * 16 + 8);
            CPA(vdst + r * 80 + c * 32, Vt + r * 32 + c * 16);
            CPA(vdst + r * 80 + c * 32 + 16, Vt + r * 32 + c * 16 + 8);
            CPC();
        }

        const uint32_t ksb = sb + ((t & 1) ? SMK1 : SMK0);
        const uint32_t vsb = sb + ((t & 1) ? SMV1 : SMV0);

        const float bh0 = BHs[(m0 + rr) * 68 + 2 * t + h];
        const float bh1 = BHs[(m0 + rr + 8) * 68 + 2 * t + h];

        // ---- S = bias + Q K^T ----
        float c[8][4];
#pragma unroll
        for (int nb = 0; nb < 8; nb++) {
            float2 w0 = *reinterpret_cast<const float2*>(&BWs[(m0 + rr) * 68 + 8 * nb + 2 * q4]);
            float2 w1 = *reinterpret_cast<const float2*>(&BWs[(m0 + rr + 8) * 68 + 8 * nb + 2 * q4]);
            c[nb][0] = w0.x + bh0;
            c[nb][1] = w0.y + bh0;
            c[nb][2] = w1.x + bh1;
            c[nb][3] = w1.y + bh1;
            uint32_t kb[4];
            ldsm4(kb, ksb + (64 * h + 8 * nb + (lane & 7)) * 80 + (lane >> 3) * 16);
            mma_f16(c[nb], aQ[0], kb[0], kb[1]);
            mma_f16(c[nb], aQ[1], kb[2], kb[3]);
        }

        // ---- P = 2^S; row sums ----
#pragma unroll
        for (int nb = 0; nb < 8; nb++) {
            float p0 = ex2f(c[nb][0]);
            float p1 = ex2f(c[nb][1]);
            float p2 = ex2f(c[nb][2]);
            float p3 = ex2f(c[nb][3]);
            l0 += p0 + p1;
            l1 += p2 + p3;
            c[nb][0] = p0;
            c[nb][1] = p1;
            c[nb][2] = p2;
            c[nb][3] = p3;
        }

        // ---- O += P V ----
#pragma unroll
        for (int kc = 0; kc < 4; kc++) {
            uint32_t pa[4];
            pa[0] = pkh2(c[2 * kc][0], c[2 * kc][1]);
            pa[1] = pkh2(c[2 * kc][2], c[2 * kc][3]);
            pa[2] = pkh2(c[2 * kc + 1][0], c[2 * kc + 1][1]);
            pa[3] = pkh2(c[2 * kc + 1][2], c[2 * kc + 1][3]);

            int key = 64 * h + 16 * kc + ((lane >> 3) & 1) * 8 + (lane & 7);
            uint32_t a1 = vsb + key * 80 + (lane >> 4) * 16;
            uint32_t vb1[4], vb2[4];
            ldsm4t(vb1, a1);
            ldsm4t(vb2, a1 + 32);
            mma_f16(o[0], pa, vb1[0], vb1[1]);
            mma_f16(o[1], pa, vb1[2], vb1[3]);
            mma_f16(o[2], pa, vb2[0], vb2[1]);
            mma_f16(o[3], pa, vb2[2], vb2[3]);
        }
    }

    // ---- reduce lsum across quad ----
    l0 += __shfl_xor_sync(0xffffffffu, l0, 1);
    l0 += __shfl_xor_sync(0xffffffffu, l0, 2);
    l1 += __shfl_xor_sync(0xffffffffu, l1, 1);
    l1 += __shfl_xor_sync(0xffffffffu, l1, 2);

    // ---- combine key-halves via smem (reuses K0 buffer) ----
    __syncthreads();
    if (h == 1) {
        float* red = reinterpret_cast<float*>(sm + SMRED) + ((size_t)(rw * 32 + lane)) * 20;
#pragma unroll
        for (int nb = 0; nb < 4; nb++)
#pragma unroll
            for (int j = 0; j < 4; j++) red[4 * nb + j] = o[nb][j];
        red[16] = l0;
        red[17] = l1;
    }
    __syncthreads();
    if (h == 0) {
        const float* red = reinterpret_cast<const float*>(sm + SMRED) + ((size_t)(rw * 32 + lane)) * 20;
#pragma unroll
        for (int nb = 0; nb < 4; nb++)
#pragma unroll
            for (int j = 0; j < 4; j++) o[nb][j] += red[4 * nb + j];
        const float inv0 = 1.f / (l0 + red[16]);
        const float inv1 = 1.f / (l1 + red[17]);

        const int b = bn >> 2, n = bn & 3;
        const int r0 = qb * 64 + m0 + rr;
        float* op0 = out + ((size_t)b * LSEQ + r0) * 128 + n * 32 + 2 * q4;
        float* op1 = op0 + 8 * 128;
#pragma unroll
        for (int nb = 0; nb < 4; nb++) {
            float2 v0, v1;
            v0.x = o[nb][0] * inv0;
            v0.y = o[nb][1] * inv0;
            v1.x = o[nb][2] * inv1;
            v1.y = o[nb][3] * inv1;
            *reinterpret_cast<float2*>(op0 + 8 * nb) = v0;
            *reinterpret_cast<float2*>(op1 + 8 * nb) = v1;
        }
    }
}

// ---------------------------------------------------------------------------
extern "C" void kernel_launch(void* const* d_in, const int* in_sizes, int n_in,
                              void* d_out, int out_size) {
    const float* x = (const float*)d_in[0];      // [2,64,64,128]
    const float* w = (const float*)d_in[1];      // [128,384]
    const float* peh = (const float*)d_in[2];    // [127,32]
    const float* pew = (const float*)d_in[3];    // [127,32]
    float* out = (float*)d_out;                  // [2,64,64,128] fp32

    cudaFuncSetAttribute(attn_kernel, cudaFuncAttributeMaxDynamicSharedMemorySize,
                         SMTOT);

    qkv_kernel<<<dim3(3, 128), 256>>>(x, w);
    attn_kernel<<<dim3(64, 8), 256, SMTOT>>>(peh, pew, out);
}

// round 9
// speedup vs baseline: 1.2513x; 1.2513x over previous
#include <cuda_runtime.h>
#include <cuda_fp16.h>
#include <cstdint>

#define NH 4
#define KD 32
#define LSEQ 4096
#define NT 32
#define LOG2E 1.4426950408889634f

// Scratch (allocation-free rule: __device__ globals)
__device__ __half g_Q[2 * NH * LSEQ * KD];  // f16 q
__device__ __half g_K[2 * NH * LSEQ * KD];  // f16 k * scale * log2e
__device__ __half g_V[2 * NH * LSEQ * KD];  // f16 v

// ---------------------------------------------------------------------------
// helpers
// ---------------------------------------------------------------------------
__device__ __forceinline__ uint32_t s2u(const void* p) {
    uint32_t a;
    asm("{ .reg .u64 t; cvta.to.shared.u64 t, %1; cvt.u32.u64 %0, t; }" : "=r"(a) : "l"(p));
    return a;
}
__device__ __forceinline__ float ex2f(float x) {
    float y;
    asm("ex2.approx.f32 %0, %1;" : "=f"(y) : "f"(x));
    return y;
}
__device__ __forceinline__ uint32_t pkh2(float lo, float hi) {
    uint32_t d;
    asm("cvt.rn.f16x2.f32 %0, %1, %2;" : "=r"(d) : "f"(hi), "f"(lo));
    return d;
}
#define CPA(dst, src) asm volatile("cp.async.cg.shared.global [%0], [%1], 16;" ::"r"(dst), "l"(src))
#define CPC() asm volatile("cp.async.commit_group;" ::: "memory")
#define CPW0() asm volatile("cp.async.wait_group 0;" ::: "memory")

__device__ __forceinline__ void mma_f16(float* c, const uint32_t* a, uint32_t b0, uint32_t b1) {
    asm volatile(
        "mma.sync.aligned.m16n8k16.row.col.f32.f16.f16.f32 "
        "{%0,%1,%2,%3}, {%4,%5,%6,%7}, {%8,%9}, {%0,%1,%2,%3};"
        : "+f"(c[0]), "+f"(c[1]), "+f"(c[2]), "+f"(c[3])
        : "r"(a[0]), "r"(a[1]), "r"(a[2]), "r"(a[3]), "r"(b0), "r"(b1));
}
__device__ __forceinline__ void ldsm4(uint32_t* r, uint32_t addr) {
    asm volatile("ldmatrix.sync.aligned.m8n8.x4.shared.b16 {%0,%1,%2,%3}, [%4];"
                 : "=r"(r[0]), "=r"(r[1]), "=r"(r[2]), "=r"(r[3]) : "r"(addr));
}
__device__ __forceinline__ void ldsm4t(uint32_t* r, uint32_t addr) {
    asm volatile("ldmatrix.sync.aligned.m8n8.x4.trans.shared.b16 {%0,%1,%2,%3}, [%4];"
                 : "=r"(r[0]), "=r"(r[1]), "=r"(r[2]), "=r"(r[3]) : "r"(addr));
}

// ---------------------------------------------------------------------------
// QKV projection as f16 HMMA GEMM: C[8192,384] = X[8192,128] @ W[128,384].
// Grid (3, 64): blockIdx.x = output segment (0:Q 1:K 2:V), blockIdx.y = 128-row
// tile. Whole K=128 resident in smem (one load, no k-loop over gmem).
// 256 threads = 8 warps in 4(M)x2(N) grid; warp tile 32x64.
// ---------------------------------------------------------------------------
#define QSM_X 0
#define QSM_W 34816
#define QSM_TOT 69632

__global__ __launch_bounds__(256) void qkv_kernel(const float* __restrict__ x,
                                                  const float* __restrict__ w) {
    extern __shared__ char qsm[];
    const uint32_t sb = s2u(qsm);
    const int tid = threadIdx.x;
    const int wid = tid >> 5;
    const int lane = tid & 31;
    const int q4 = lane & 3;
    const int rr = lane >> 2;
    const int cb = blockIdx.x;    // segment: 0=Q 1=K 2=V
    const int mblk = blockIdx.y;  // row tile
    const int mw = (wid & 3) * 32;
    const int nw = (wid >> 2) * 64;

    // ---- load X tile [128 rows][128 k] and W tile [128 k][128 n] as f16 ----
    const float4* Xf4 = reinterpret_cast<const float4*>(x) + (size_t)mblk * 128 * 32;
    const float4* Wf4 = reinterpret_cast<const float4*>(w);
#pragma unroll
    for (int i = 0; i < 16; i++) {
        int u = tid + 256 * i;
        int r = u >> 5, c4 = u & 31;
        float4 vx = Xf4[r * 32 + c4];
        uint2 px = {pkh2(vx.x, vx.y), pkh2(vx.z, vx.w)};
        *reinterpret_cast<uint2*>(qsm + QSM_X + r * 272 + c4 * 8) = px;
        float4 vw = Wf4[r * 96 + cb * 32 + c4];
        uint2 pw = {pkh2(vw.x, vw.y), pkh2(vw.z, vw.w)};
        *reinterpret_cast<uint2*>(qsm + QSM_W + r * 272 + c4 * 8) = pw;
    }
    __syncthreads();

    // ---- compute: 8 k16 chunks, warp tile 32x64 ----
    float c0[8][4], c1[8][4];
#pragma unroll
    for (int f = 0; f < 8; f++)
#pragma unroll
        for (int j = 0; j < 4; j++) {
            c0[f][j] = 0.f;
            c1[f][j] = 0.f;
        }

#pragma unroll
    for (int kc = 0; kc < 8; kc++) {
        uint32_t a0[4], a1[4];
        ldsm4(a0, sb + QSM_X + (mw + (lane & 15)) * 272 + kc * 32 + (lane >> 4) * 16);
        ldsm4(a1, sb + QSM_X + (mw + 16 + (lane & 15)) * 272 + kc * 32 + (lane >> 4) * 16);

        int krow = kc * 16 + ((lane >> 3) & 1) * 8 + (lane & 7);
        uint32_t baddr = sb + QSM_W + krow * 272 + nw * 2 + (lane >> 4) * 16;
        uint32_t b01[4], b23[4], b45[4], b67[4];
        ldsm4t(b01, baddr);
        ldsm4t(b23, baddr + 32);
        ldsm4t(b45, baddr + 64);
        ldsm4t(b67, baddr + 96);

        mma_f16(c0[0], a0, b01[0], b01[1]);
        mma_f16(c1[0], a1, b01[0], b01[1]);
        mma_f16(c0[1], a0, b01[2], b01[3]);
        mma_f16(c1[1], a1, b01[2], b01[3]);
        mma_f16(c0[2], a0, b23[0], b23[1]);
        mma_f16(c1[2], a1, b23[0], b23[1]);
        mma_f16(c0[3], a0, b23[2], b23[3]);
        mma_f16(c1[3], a1, b23[2], b23[3]);
        mma_f16(c0[4], a0, b45[0], b45[1]);
        mma_f16(c1[4], a1, b45[0], b45[1]);
        mma_f16(c0[5], a0, b45[2], b45[3]);
        mma_f16(c1[5], a1, b45[2], b45[3]);
        mma_f16(c0[6], a0, b67[0], b67[1]);
        mma_f16(c1[6], a1, b67[0], b67[1]);
        mma_f16(c0[7], a0, b67[2], b67[3]);
        mma_f16(c1[7], a1, b67[2], b67[3]);
    }

    // ---- scatter to g_Q / g_K / g_V ----
    const float kscale = 0.17677669529663688f * LOG2E;
    const float sc = (cb == 1) ? kscale : 1.f;
    __half* seg = (cb == 0) ? g_Q : (cb == 1) ? g_K : g_V;

#pragma unroll
    for (int f = 0; f < 8; f++) {
        int col = nw + 8 * f + 2 * q4;   // 0..127 within segment
        int hd = col >> 5, d = col & 31;
#pragma unroll
        for (int part = 0; part < 2; part++) {
            // part 0: rows mw+rr / mw+rr+8 (c0); part 1: +16 (c1)
            const float* cc = part ? c1[f] : c0[f];
            int mbase = mblk * 128 + mw + 16 * part + rr;
#pragma unroll
            for (int half = 0; half < 2; half++) {
                int m = mbase + 8 * half;
                int b = m >> 12, l = m & 4095;
                uint32_t pk = pkh2(cc[2 * half] * sc, cc[2 * half + 1] * sc);
                *reinterpret_cast<uint32_t*>(
                    seg + (((size_t)(b * NH + hd)) * LSEQ + l) * KD + d) = pk;
            }
        }
    }
}

// ---------------------------------------------------------------------------
// f16 HMMA flash attention, 512 threads = 16 warps (R5 layout, measured best).
// warp w: rowgroup rw = w&7 (16 query rows), key-half h = w>>3 (64 keys/tile).
// ---------------------------------------------------------------------------
#define SMQ 0
#define SMK0 10240
#define SMK1 20480
#define SMV0 30720
#define SMV1 40960
#define SMBW 51200
#define SMBH 86016
#define SMTOT 120832
// overlays (consumed before K/V buffers first written)
#define SMPH 10240
#define SMPW 30720
#define SMRED 10240

__global__ __launch_bounds__(512, 1) void attn_kernel(const float* __restrict__ peh,
                                                      const float* __restrict__ pew,
                                                      float* __restrict__ out) {
    extern __shared__ char sm[];
    const uint32_t sb = s2u(sm);
    const int tid = threadIdx.x;
    const int wid = tid >> 5;
    const int lane = tid & 31;
    const int q4 = lane & 3;
    const int rr = lane >> 2;
    const int qb = blockIdx.x;    // 0..31
    const int bn = blockIdx.y;    // 0..7
    const int rw = wid & 7;
    const int h = wid >> 3;       // key-half
    const int m0 = rw * 16;

    const __half* Qg = g_Q + ((size_t)bn * LSEQ + (size_t)qb * 128) * KD;
    const __half* Kg = g_K + (size_t)bn * LSEQ * KD;
    const __half* Vg = g_V + (size_t)bn * LSEQ * KD;

    // ---- prologue: Q tile (f16, 80B rows) + pos tables (fp32, 144B rows) ----
    {
        int r = tid >> 2, c = tid & 3;
        CPA(sb + SMQ + r * 80 + c * 16, Qg + r * 32 + c * 8);
    }
    for (int u = tid; u < 1016; u += 512) {
        int r = u >> 3, c = u & 7;
        CPA(sb + SMPH + r * 144 + c * 16, peh + r * 32 + 4 * c);
        CPA(sb + SMPW + r * 144 + c * 16, pew + r * 32 + 4 * c);
    }
    CPC();
    CPW0();
    __syncthreads();

    // ---- bias precompute (x log2e): BW[q][kj], BH[q][ki]: [128][68] fp32 ----
    {
        int pair = tid >> 1, hc = tid & 1;
        int table = pair >> 7, qq = pair & 127;
        const __half2* qrow = reinterpret_cast<const __half2*>(sm + SMQ + qq * 80);
        float2 qv[16];
#pragma unroll
        for (int i = 0; i < 16; i++) qv[i] = __half22float2(qrow[i]);
        const float* tab = reinterpret_cast<const float*>(sm + (table ? SMPH : SMPW));
        int base = table ? (63 - 2 * qb - (qq >> 6)) : (63 - (qq & 63));
        float* dst = reinterpret_cast<float*>(sm + (table ? SMBH : SMBW)) + qq * 68;
        for (int kc = 32 * hc; kc < 32 * hc + 32; kc++) {
            const float* er = tab + (base + kc) * 36;
            float s = 0.f;
#pragma unroll
            for (int i = 0; i < 8; i++) {
                float4 e = *reinterpret_cast<const float4*>(&er[4 * i]);
                s = fmaf(qv[2 * i].x, e.x, s);
                s = fmaf(qv[2 * i].y, e.y, s);
                s = fmaf(qv[2 * i + 1].x, e.z, s);
                s = fmaf(qv[2 * i + 1].y, e.w, s);
            }
            dst[kc] = s * LOG2E;
        }
    }
    __syncthreads();

    // ---- Q A-fragments (m16k16 x2 chunks), fixed for all tiles ----
    uint32_t aQ[2][4];
#pragma unroll
    for (int kc = 0; kc < 2; kc++)
        ldsm4(aQ[kc], sb + SMQ + (m0 + (lane & 15)) * 80 + kc * 32 + (lane >> 4) * 16);

    // ---- issue K/V tile 0 ----
    {
        int r = tid >> 2, c = tid & 3;
        CPA(sb + SMK0 + r * 80 + c * 16, Kg + r * 32 + c * 8);
        CPA(sb + SMV0 + r * 80 + c * 16, Vg + r * 32 + c * 8);
    }
    CPC();

    const float* BWs = reinterpret_cast<const float*>(sm + SMBW);
    const float* BHs = reinterpret_cast<const float*>(sm + SMBH);

    float o[4][4];
#pragma unroll
    for (int i = 0; i < 4; i++)
#pragma unroll
        for (int j = 0; j < 4; j++) o[i][j] = 0.f;
    float l0 = 0.f, l1 = 0.f;

    for (int t = 0; t < NT; t++) {
        CPW0();
        __syncthreads();
        if (t + 1 < NT) {
            const int nb = (t + 1) & 1;
            const __half* Kt = Kg + (size_t)(t + 1) * 128 * KD;
            const __half* Vt = Vg + (size_t)(t + 1) * 128 * KD;
            int r = tid >> 2, c = tid & 3;
            CPA(sb + (nb ? SMK1 : SMK0) + r * 80 + c * 16, Kt + r * 32 + c * 8);
            CPA(sb + (nb ? SMV1 : SMV0) + r * 80 + c * 16, Vt + r * 32 + c * 8);
            CPC();
        }

        const uint32_t ksb = sb + ((t & 1) ? SMK1 : SMK0);
        const uint32_t vsb = sb + ((t & 1) ? SMV1 : SMV0);

        const float bh0 = BHs[(m0 + rr) * 68 + 2 * t + h];
        const float bh1 = BHs[(m0 + rr + 8) * 68 + 2 * t + h];

        // ---- S = bias + Q K^T ----
        float c[8][4];
#pragma unroll
        for (int nb = 0; nb < 8; nb++) {
            float2 w0 = *reinterpret_cast<const float2*>(&BWs[(m0 + rr) * 68 + 8 * nb + 2 * q4]);
            float2 w1 = *reinterpret_cast<const float2*>(&BWs[(m0 + rr + 8) * 68 + 8 * nb + 2 * q4]);
            c[nb][0] = w0.x + bh0;
            c[nb][1] = w0.y + bh0;
            c[nb][2] = w1.x + bh1;
            c[nb][3] = w1.y + bh1;
            uint32_t kb[4];
            ldsm4(kb, ksb + (64 * h + 8 * nb + (lane & 7)) * 80 + (lane >> 3) * 16);
            mma_f16(c[nb], aQ[0], kb[0], kb[1]);
            mma_f16(c[nb], aQ[1], kb[2], kb[3]);
        }

        // ---- P = 2^S; row sums ----
#pragma unroll
        for (int nb = 0; nb < 8; nb++) {
            float p0 = ex2f(c[nb][0]);
            float p1 = ex2f(c[nb][1]);
            float p2 = ex2f(c[nb][2]);
            float p3 = ex2f(c[nb][3]);
            l0 += p0 + p1;
            l1 += p2 + p3;
            c[nb][0] = p0;
            c[nb][1] = p1;
            c[nb][2] = p2;
            c[nb][3] = p3;
        }

        // ---- O += P V ----
#pragma unroll
        for (int kc = 0; kc < 4; kc++) {
            uint32_t pa[4];
            pa[0] = pkh2(c[2 * kc][0], c[2 * kc][1]);
            pa[1] = pkh2(c[2 * kc][2], c[2 * kc][3]);
            pa[2] = pkh2(c[2 * kc + 1][0], c[2 * kc + 1][1]);
            pa[3] = pkh2(c[2 * kc + 1][2], c[2 * kc + 1][3]);

            int key = 64 * h + 16 * kc + ((lane >> 3) & 1) * 8 + (lane & 7);
            uint32_t a1 = vsb + key * 80 + (lane >> 4) * 16;
            uint32_t vb1[4], vb2[4];
            ldsm4t(vb1, a1);
            ldsm4t(vb2, a1 + 32);
            mma_f16(o[0], pa, vb1[0], vb1[1]);
            mma_f16(o[1], pa, vb1[2], vb1[3]);
            mma_f16(o[2], pa, vb2[0], vb2[1]);
            mma_f16(o[3], pa, vb2[2], vb2[3]);
        }
    }

    // ---- reduce lsum across quad ----
    l0 += __shfl_xor_sync(0xffffffffu, l0, 1);
    l0 += __shfl_xor_sync(0xffffffffu, l0, 2);
    l1 += __shfl_xor_sync(0xffffffffu, l1, 1);
    l1 += __shfl_xor_sync(0xffffffffu, l1, 2);

    // ---- combine key-halves via smem (reuses K buffers) ----
    __syncthreads();
    if (h == 1) {
        float* red = reinterpret_cast<float*>(sm + SMRED) + ((size_t)(rw * 32 + lane)) * 20;
#pragma unroll
        for (int nb = 0; nb < 4; nb++)
#pragma unroll
            for (int j = 0; j < 4; j++) red[4 * nb + j] = o[nb][j];
        red[16] = l0;
        red[17] = l1;
    }
    __syncthreads();
    if (h == 0) {
        const float* red = reinterpret_cast<const float*>(sm + SMRED) + ((size_t)(rw * 32 + lane)) * 20;
#pragma unroll
        for (int nb = 0; nb < 4; nb++)
#pragma unroll
            for (int j = 0; j < 4; j++) o[nb][j] += red[4 * nb + j];
        const float inv0 = 1.f / (l0 + red[16]);
        const float inv1 = 1.f / (l1 + red[17]);

        const int b = bn >> 2, n = bn & 3;
        const int r0 = qb * 128 + m0 + rr;
        float* op0 = out + ((size_t)b * LSEQ + r0) * 128 + n * 32 + 2 * q4;
        float* op1 = op0 + 8 * 128;
#pragma unroll
        for (int nb = 0; nb < 4; nb++) {
            float2 v0, v1;
            v0.x = o[nb][0] * inv0;
            v0.y = o[nb][1] * inv0;
            v1.x = o[nb][2] * inv1;
            v1.y = o[nb][3] * inv1;
            *reinterpret_cast<float2*>(op0 + 8 * nb) = v0;
            *reinterpret_cast<float2*>(op1 + 8 * nb) = v1;
        }
    }
}

// ---------------------------------------------------------------------------
extern "C" void kernel_launch(void* const* d_in, const int* in_sizes, int n_in,
                              void* d_out, int out_size) {
    const float* x = (const float*)d_in[0];      // [2,64,64,128]
    const float* w = (const float*)d_in[1];      // [128,384]
    const float* peh = (const float*)d_in[2];    // [127,32]
    const float* pew = (const float*)d_in[3];    // [127,32]
    float* out = (float*)d_out;                  // [2,64,64,128] fp32

    cudaFuncSetAttribute(qkv_kernel, cudaFuncAttributeMaxDynamicSharedMemorySize,
                         QSM_TOT);
    cudaFuncSetAttribute(attn_kernel, cudaFuncAttributeMaxDynamicSharedMemorySize,
                         SMTOT);

    qkv_kernel<<<dim3(3, 64), 256, QSM_TOT>>>(x, w);
    attn_kernel<<<dim3(32, 8), 512, SMTOT>>>(peh, pew, out);
}

// round 11
// speedup vs baseline: 1.2828x; 1.0251x over previous
#include <cuda_runtime.h>
#include <cuda_fp16.h>
#include <cstdint>

#define NH 4
#define KD 32
#define LSEQ 4096
#define NT 32
#define LOG2E 1.4426950408889634f

// Scratch (allocation-free rule: __device__ globals)
__device__ __half g_Q[2 * NH * LSEQ * KD];  // f16 q
__device__ __half g_K[2 * NH * LSEQ * KD];  // f16 k * scale * log2e
__device__ __half g_V[2 * NH * LSEQ * KD];  // f16 v

// ---------------------------------------------------------------------------
// helpers
// ---------------------------------------------------------------------------
__device__ __forceinline__ uint32_t s2u(const void* p) {
    uint32_t a;
    asm("{ .reg .u64 t; cvta.to.shared.u64 t, %1; cvt.u32.u64 %0, t; }" : "=r"(a) : "l"(p));
    return a;
}
__device__ __forceinline__ float ex2f(float x) {
    float y;
    asm("ex2.approx.f32 %0, %1;" : "=f"(y) : "f"(x));
    return y;
}
__device__ __forceinline__ uint32_t pkh2(float lo, float hi) {
    uint32_t d;
    asm("cvt.rn.f16x2.f32 %0, %1, %2;" : "=r"(d) : "f"(hi), "f"(lo));
    return d;
}
#define CPA(dst, src) asm volatile("cp.async.cg.shared.global [%0], [%1], 16;" ::"r"(dst), "l"(src))
#define CPC() asm volatile("cp.async.commit_group;" ::: "memory")
#define CPW0() asm volatile("cp.async.wait_group 0;" ::: "memory")

__device__ __forceinline__ void mma_f16(float* c, const uint32_t* a, uint32_t b0, uint32_t b1) {
    asm volatile(
        "mma.sync.aligned.m16n8k16.row.col.f32.f16.f16.f32 "
        "{%0,%1,%2,%3}, {%4,%5,%6,%7}, {%8,%9}, {%0,%1,%2,%3};"
        : "+f"(c[0]), "+f"(c[1]), "+f"(c[2]), "+f"(c[3])
        : "r"(a[0]), "r"(a[1]), "r"(a[2]), "r"(a[3]), "r"(b0), "r"(b1));
}
__device__ __forceinline__ void ldsm4(uint32_t* r, uint32_t addr) {
    asm volatile("ldmatrix.sync.aligned.m8n8.x4.shared.b16 {%0,%1,%2,%3}, [%4];"
                 : "=r"(r[0]), "=r"(r[1]), "=r"(r[2]), "=r"(r[3]) : "r"(addr));
}
__device__ __forceinline__ void ldsm4t(uint32_t* r, uint32_t addr) {
    asm volatile("ldmatrix.sync.aligned.m8n8.x4.trans.shared.b16 {%0,%1,%2,%3}, [%4];"
                 : "=r"(r[0]), "=r"(r[1]), "=r"(r[2]), "=r"(r[3]) : "r"(addr));
}

// ---------------------------------------------------------------------------
// QKV projection as f16 HMMA GEMM: C[8192,384] = X[8192,128] @ W[128,384].
// Grid (3, 64): blockIdx.x = output segment (0:Q 1:K 2:V), blockIdx.y = 128-row
// tile. Whole K=128 resident in smem (one load, no k-loop over gmem).
// 256 threads = 8 warps in 4(M)x2(N) grid; warp tile 32x64.
// ---------------------------------------------------------------------------
#define QSM_X 0
#define QSM_W 34816
#define QSM_TOT 69632

__global__ __launch_bounds__(256) void qkv_kernel(const float* __restrict__ x,
                                                  const float* __restrict__ w) {
    extern __shared__ char qsm[];
    const uint32_t sb = s2u(qsm);
    const int tid = threadIdx.x;
    const int wid = tid >> 5;
    const int lane = tid & 31;
    const int q4 = lane & 3;
    const int rr = lane >> 2;
    const int cb = blockIdx.x;    // segment: 0=Q 1=K 2=V
    const int mblk = blockIdx.y;  // row tile
    const int mw = (wid & 3) * 32;
    const int nw = (wid >> 2) * 64;

    // ---- load X tile [128 rows][128 k] and W tile [128 k][128 n] as f16 ----
    const float4* Xf4 = reinterpret_cast<const float4*>(x) + (size_t)mblk * 128 * 32;
    const float4* Wf4 = reinterpret_cast<const float4*>(w);
#pragma unroll
    for (int i = 0; i < 16; i++) {
        int u = tid + 256 * i;
        int r = u >> 5, c4 = u & 31;
        float4 vx = Xf4[r * 32 + c4];
        uint2 px = {pkh2(vx.x, vx.y), pkh2(vx.z, vx.w)};
        *reinterpret_cast<uint2*>(qsm + QSM_X + r * 272 + c4 * 8) = px;
        float4 vw = Wf4[r * 96 + cb * 32 + c4];
        uint2 pw = {pkh2(vw.x, vw.y), pkh2(vw.z, vw.w)};
        *reinterpret_cast<uint2*>(qsm + QSM_W + r * 272 + c4 * 8) = pw;
    }
    __syncthreads();

    // ---- compute: 8 k16 chunks, warp tile 32x64 ----
    float c0[8][4], c1[8][4];
#pragma unroll
    for (int f = 0; f < 8; f++)
#pragma unroll
        for (int j = 0; j < 4; j++) {
            c0[f][j] = 0.f;
            c1[f][j] = 0.f;
        }

#pragma unroll
    for (int kc = 0; kc < 8; kc++) {
        uint32_t a0[4], a1[4];
        ldsm4(a0, sb + QSM_X + (mw + (lane & 15)) * 272 + kc * 32 + (lane >> 4) * 16);
        ldsm4(a1, sb + QSM_X + (mw + 16 + (lane & 15)) * 272 + kc * 32 + (lane >> 4) * 16);

        int krow = kc * 16 + ((lane >> 3) & 1) * 8 + (lane & 7);
        uint32_t baddr = sb + QSM_W + krow * 272 + nw * 2 + (lane >> 4) * 16;
        uint32_t b01[4], b23[4], b45[4], b67[4];
        ldsm4t(b01, baddr);
        ldsm4t(b23, baddr + 32);
        ldsm4t(b45, baddr + 64);
        ldsm4t(b67, baddr + 96);

        mma_f16(c0[0], a0, b01[0], b01[1]);
        mma_f16(c1[0], a1, b01[0], b01[1]);
        mma_f16(c0[1], a0, b01[2], b01[3]);
        mma_f16(c1[1], a1, b01[2], b01[3]);
        mma_f16(c0[2], a0, b23[0], b23[1]);
        mma_f16(c1[2], a1, b23[0], b23[1]);
        mma_f16(c0[3], a0, b23[2], b23[3]);
        mma_f16(c1[3], a1, b23[2], b23[3]);
        mma_f16(c0[4], a0, b45[0], b45[1]);
        mma_f16(c1[4], a1, b45[0], b45[1]);
        mma_f16(c0[5], a0, b45[2], b45[3]);
        mma_f16(c1[5], a1, b45[2], b45[3]);
        mma_f16(c0[6], a0, b67[0], b67[1]);
        mma_f16(c1[6], a1, b67[0], b67[1]);
        mma_f16(c0[7], a0, b67[2], b67[3]);
        mma_f16(c1[7], a1, b67[2], b67[3]);
    }

    // ---- scatter to g_Q / g_K / g_V ----
    const float kscale = 0.17677669529663688f * LOG2E;
    const float sc = (cb == 1) ? kscale : 1.f;
    __half* seg = (cb == 0) ? g_Q : (cb == 1) ? g_K : g_V;

#pragma unroll
    for (int f = 0; f < 8; f++) {
        int col = nw + 8 * f + 2 * q4;   // 0..127 within segment
        int hd = col >> 5, d = col & 31;
#pragma unroll
        for (int part = 0; part < 2; part++) {
            const float* cc = part ? c1[f] : c0[f];
            int mbase = mblk * 128 + mw + 16 * part + rr;
#pragma unroll
            for (int half = 0; half < 2; half++) {
                int m = mbase + 8 * half;
                int b = m >> 12, l = m & 4095;
                uint32_t pk = pkh2(cc[2 * half] * sc, cc[2 * half + 1] * sc);
                *reinterpret_cast<uint32_t*>(
                    seg + (((size_t)(b * NH + hd)) * LSEQ + l) * KD + d) = pk;
            }
        }
    }
}

// ---------------------------------------------------------------------------
// f16 HMMA flash attention, 512 threads = 16 warps (R5 layout).
// warp w: rowgroup rw = w&7 (16 query rows), key-half h = w>>3 (64 keys/tile).
// BW bias table stored f16 with 72-half row stride => conflict-free LDS.32.
// ---------------------------------------------------------------------------
#define SMQ 0
#define SMK0 10240
#define SMK1 20480
#define SMV0 30720
#define SMV1 40960
#define SMBW 51200   /* f16 [128][72] = 18432 B */
#define SMBH 69632   /* f32 [128][68] = 34816 B */
#define SMTOT 104448
// overlays (consumed before K/V buffers first written)
#define SMPH 10240
#define SMPW 30720
#define SMRED 10240

__global__ __launch_bounds__(512, 1) void attn_kernel(const float* __restrict__ peh,
                                                      const float* __restrict__ pew,
                                                      float* __restrict__ out) {
    extern __shared__ char sm[];
    const uint32_t sb = s2u(sm);
    const int tid = threadIdx.x;
    const int wid = tid >> 5;
    const int lane = tid & 31;
    const int q4 = lane & 3;
    const int rr = lane >> 2;
    const int qb = blockIdx.x;    // 0..31
    const int bn = blockIdx.y;    // 0..7
    const int rw = wid & 7;
    const int h = wid >> 3;       // key-half
    const int m0 = rw * 16;

    const __half* Qg = g_Q + ((size_t)bn * LSEQ + (size_t)qb * 128) * KD;
    const __half* Kg = g_K + (size_t)bn * LSEQ * KD;
    const __half* Vg = g_V + (size_t)bn * LSEQ * KD;

    // ---- prologue: Q tile (f16, 80B rows) + pos tables (fp32, 144B rows) ----
    {
        int r = tid >> 2, c = tid & 3;
        CPA(sb + SMQ + r * 80 + c * 16, Qg + r * 32 + c * 8);
    }
    for (int u = tid; u < 1016; u += 512) {
        int r = u >> 3, c = u & 7;
        CPA(sb + SMPH + r * 144 + c * 16, peh + r * 32 + 4 * c);
        CPA(sb + SMPW + r * 144 + c * 16, pew + r * 32 + 4 * c);
    }
    CPC();
    CPW0();
    __syncthreads();

    // ---- bias precompute (x log2e): BW f16 [128][72], BH f32 [128][68] ----
    {
        int pair = tid >> 1, hc = tid & 1;
        int table = pair >> 7, qq = pair & 127;
        const __half2* qrow = reinterpret_cast<const __half2*>(sm + SMQ + qq * 80);
        float2 qv[16];
#pragma unroll
        for (int i = 0; i < 16; i++) qv[i] = __half22float2(qrow[i]);
        const float* tab = reinterpret_cast<const float*>(sm + (table ? SMPH : SMPW));
        int base = table ? (63 - 2 * qb - (qq >> 6)) : (63 - (qq & 63));
        __half* dstw = reinterpret_cast<__half*>(sm + SMBW) + qq * 72;
        float* dsth = reinterpret_cast<float*>(sm + SMBH) + qq * 68;
        for (int kc = 32 * hc; kc < 32 * hc + 32; kc++) {
            const float* er = tab + (base + kc) * 36;
            float s = 0.f;
#pragma unroll
            for (int i = 0; i < 8; i++) {
                float4 e = *reinterpret_cast<const float4*>(&er[4 * i]);
                s = fmaf(qv[2 * i].x, e.x, s);
                s = fmaf(qv[2 * i].y, e.y, s);
                s = fmaf(qv[2 * i + 1].x, e.z, s);
                s = fmaf(qv[2 * i + 1].y, e.w, s);
            }
            s *= LOG2E;
            if (table)
                dsth[kc] = s;
            else
                dstw[kc] = __float2half_rn(s);
        }
    }
    __syncthreads();

    // ---- Q A-fragments (m16k16 x2 chunks), fixed for all tiles ----
    uint32_t aQ[2][4];
#pragma unroll
    for (int kc = 0; kc < 2; kc++)
        ldsm4(aQ[kc], sb + SMQ + (m0 + (lane & 15)) * 80 + kc * 32 + (lane >> 4) * 16);

    // ---- issue K/V tile 0 ----
    {
        int r = tid >> 2, c = tid & 3;
        CPA(sb + SMK0 + r * 80 + c * 16, Kg + r * 32 + c * 8);
        CPA(sb + SMV0 + r * 80 + c * 16, Vg + r * 32 + c * 8);
    }
    CPC();

    const __half2* BW2 = reinterpret_cast<const __half2*>(sm + SMBW);  // stride 36 h2
    const float* BHs = reinterpret_cast<const float*>(sm + SMBH);

    float o[4][4];
#pragma unroll
    for (int i = 0; i < 4; i++)
#pragma unroll
        for (int j = 0; j < 4; j++) o[i][j] = 0.f;
    float l0 = 0.f, l1 = 0.f;

    for (int t = 0; t < NT; t++) {
        CPW0();
        __syncthreads();
        if (t + 1 < NT) {
            const int nb = (t + 1) & 1;
            const __half* Kt = Kg + (size_t)(t + 1) * 128 * KD;
            const __half* Vt = Vg + (size_t)(t + 1) * 128 * KD;
            int r = tid >> 2, c = tid & 3;
            CPA(sb + (nb ? SMK1 : SMK0) + r * 80 + c * 16, Kt + r * 32 + c * 8);
            CPA(sb + (nb ? SMV1 : SMV0) + r * 80 + c * 16, Vt + r * 32 + c * 8);
            CPC();
        }

        const uint32_t ksb = sb + ((t & 1) ? SMK1 : SMK0);
        const uint32_t vsb = sb + ((t & 1) ? SMV1 : SMV0);

        const float bh0 = BHs[(m0 + rr) * 68 + 2 * t + h];
        const float bh1 = BHs[(m0 + rr + 8) * 68 + 2 * t + h];

        // ---- S = bias + Q K^T ----
        float c[8][4];
#pragma unroll
        for (int nb = 0; nb < 8; nb++) {
            float2 w0 = __half22float2(BW2[(m0 + rr) * 36 + 4 * nb + q4]);
            float2 w1 = __half22float2(BW2[(m0 + rr + 8) * 36 + 4 * nb + q4]);
            c[nb][0] = w0.x + bh0;
            c[nb][1] = w0.y + bh0;
            c[nb][2] = w1.x + bh1;
            c[nb][3] = w1.y + bh1;
            uint32_t kb[4];
            ldsm4(kb, ksb + (64 * h + 8 * nb + (lane & 7)) * 80 + (lane >> 3) * 16);
            mma_f16(c[nb], aQ[0], kb[0], kb[1]);
            mma_f16(c[nb], aQ[1], kb[2], kb[3]);
        }

        // ---- P = 2^S; row sums ----
#pragma unroll
        for (int nb = 0; nb < 8; nb++) {
            float p0 = ex2f(c[nb][0]);
            float p1 = ex2f(c[nb][1]);
            float p2 = ex2f(c[nb][2]);
            float p3 = ex2f(c[nb][3]);
            l0 += p0 + p1;
            l1 += p2 + p3;
            c[nb][0] = p0;
            c[nb][1] = p1;
            c[nb][2] = p2;
            c[nb][3] = p3;
        }

        // ---- O += P V ----
#pragma unroll
        for (int kc = 0; kc < 4; kc++) {
            uint32_t pa[4];
            pa[0] = pkh2(c[2 * kc][0], c[2 * kc][1]);
            pa[1] = pkh2(c[2 * kc][2], c[2 * kc][3]);
            pa[2] = pkh2(c[2 * kc + 1][0], c[2 * kc + 1][1]);
            pa[3] = pkh2(c[2 * kc + 1][2], c[2 * kc + 1][3]);

            int key = 64 * h + 16 * kc + ((lane >> 3) & 1) * 8 + (lane & 7);
            uint32_t a1 = vsb + key * 80 + (lane >> 4) * 16;
            uint32_t vb1[4], vb2[4];
            ldsm4t(vb1, a1);
            ldsm4t(vb2, a1 + 32);
            mma_f16(o[0], pa, vb1[0], vb1[1]);
            mma_f16(o[1], pa, vb1[2], vb1[3]);
            mma_f16(o[2], pa, vb2[0], vb2[1]);
            mma_f16(o[3], pa, vb2[2], vb2[3]);
        }
    }

    // ---- reduce lsum across quad ----
    l0 += __shfl_xor_sync(0xffffffffu, l0, 1);
    l0 += __shfl_xor_sync(0xffffffffu, l0, 2);
    l1 += __shfl_xor_sync(0xffffffffu, l1, 1);
    l1 += __shfl_xor_sync(0xffffffffu, l1, 2);

    // ---- combine key-halves via smem (reuses K buffers) ----
    __syncthreads();
    if (h == 1) {
        float* red = reinterpret_cast<float*>(sm + SMRED) + ((size_t)(rw * 32 + lane)) * 20;
#pragma unroll
        for (int nb = 0; nb < 4; nb++)
#pragma unroll
            for (int j = 0; j < 4; j++) red[4 * nb + j] = o[nb][j];
        red[16] = l0;
        red[17] = l1;
    }
    __syncthreads();
    if (h == 0) {
        const float* red = reinterpret_cast<const float*>(sm + SMRED) + ((size_t)(rw * 32 + lane)) * 20;
#pragma unroll
        for (int nb = 0; nb < 4; nb++)
#pragma unroll
            for (int j = 0; j < 4; j++) o[nb][j] += red[4 * nb + j];
        const float inv0 = 1.f / (l0 + red[16]);
        const float inv1 = 1.f / (l1 + red[17]);

        const int b = bn >> 2, n = bn & 3;
        const int r0 = qb * 128 + m0 + rr;
        float* op0 = out + ((size_t)b * LSEQ + r0) * 128 + n * 32 + 2 * q4;
        float* op1 = op0 + 8 * 128;
#pragma unroll
        for (int nb = 0; nb < 4; nb++) {
            float2 v0, v1;
            v0.x = o[nb][0] * inv0;
            v0.y = o[nb][1] * inv0;
            v1.x = o[nb][2] * inv1;
            v1.y = o[nb][3] * inv1;
            *reinterpret_cast<float2*>(op0 + 8 * nb) = v0;
            *reinterpret_cast<float2*>(op1 + 8 * nb) = v1;
        }
    }
}

// ---------------------------------------------------------------------------
extern "C" void kernel_launch(void* const* d_in, const int* in_sizes, int n_in,
                              void* d_out, int out_size) {
    const float* x = (const float*)d_in[0];      // [2,64,64,128]
    const float* w = (const float*)d_in[1];      // [128,384]
    const float* peh = (const float*)d_in[2];    // [127,32]
    const float* pew = (const float*)d_in[3];    // [127,32]
    float* out = (float*)d_out;                  // [2,64,64,128] fp32

    cudaFuncSetAttribute(qkv_kernel, cudaFuncAttributeMaxDynamicSharedMemorySize,
                         QSM_TOT);
    cudaFuncSetAttribute(attn_kernel, cudaFuncAttributeMaxDynamicSharedMemorySize,
                         SMTOT);

    qkv_kernel<<<dim3(3, 64), 256, QSM_TOT>>>(x, w);
    attn_kernel<<<dim3(32, 8), 512, SMTOT>>>(peh, pew, out);
}

// round 13
// speedup vs baseline: 1.4183x; 1.1057x over previous
#include <cuda_runtime.h>
#include <cuda_fp16.h>
#include <cstdint>

#define NH 4
#define KD 32
#define LSEQ 4096
#define NT 32
#define LOG2E 1.4426950408889634f

// Scratch (allocation-free rule: __device__ globals)
__device__ __half g_Q[2 * NH * LSEQ * KD];  // f16 q
__device__ __half g_K[2 * NH * LSEQ * KD];  // f16 k * scale * log2e
__device__ __half g_V[2 * NH * LSEQ * KD];  // f16 v

// ---------------------------------------------------------------------------
// helpers
// ---------------------------------------------------------------------------
__device__ __forceinline__ uint32_t s2u(const void* p) {
    uint32_t a;
    asm("{ .reg .u64 t; cvta.to.shared.u64 t, %1; cvt.u32.u64 %0, t; }" : "=r"(a) : "l"(p));
    return a;
}
__device__ __forceinline__ float ex2f(float x) {
    float y;
    asm("ex2.approx.f32 %0, %1;" : "=f"(y) : "f"(x));
    return y;
}
__device__ __forceinline__ uint32_t pkh2(float lo, float hi) {
    uint32_t d;
    asm("cvt.rn.f16x2.f32 %0, %1, %2;" : "=r"(d) : "f"(hi), "f"(lo));
    return d;
}
#define CPA(dst, src) asm volatile("cp.async.cg.shared.global [%0], [%1], 16;" ::"r"(dst), "l"(src))
#define CPC() asm volatile("cp.async.commit_group;" ::: "memory")
#define CPW0() asm volatile("cp.async.wait_group 0;" ::: "memory")
#define CPW1() asm volatile("cp.async.wait_group 1;" ::: "memory")

__device__ __forceinline__ void mma_f16(float* c, const uint32_t* a, uint32_t b0, uint32_t b1) {
    asm volatile(
        "mma.sync.aligned.m16n8k16.row.col.f32.f16.f16.f32 "
        "{%0,%1,%2,%3}, {%4,%5,%6,%7}, {%8,%9}, {%0,%1,%2,%3};"
        : "+f"(c[0]), "+f"(c[1]), "+f"(c[2]), "+f"(c[3])
        : "r"(a[0]), "r"(a[1]), "r"(a[2]), "r"(a[3]), "r"(b0), "r"(b1));
}
__device__ __forceinline__ void ldsm4(uint32_t* r, uint32_t addr) {
    asm volatile("ldmatrix.sync.aligned.m8n8.x4.shared.b16 {%0,%1,%2,%3}, [%4];"
                 : "=r"(r[0]), "=r"(r[1]), "=r"(r[2]), "=r"(r[3]) : "r"(addr));
}
__device__ __forceinline__ void ldsm4t(uint32_t* r, uint32_t addr) {
    asm volatile("ldmatrix.sync.aligned.m8n8.x4.trans.shared.b16 {%0,%1,%2,%3}, [%4];"
                 : "=r"(r[0]), "=r"(r[1]), "=r"(r[2]), "=r"(r[3]) : "r"(addr));
}

// ---------------------------------------------------------------------------
// QKV projection as f16 HMMA GEMM: C[8192,384] = X[8192,128] @ W[128,384].
// ---------------------------------------------------------------------------
#define QSM_X 0
#define QSM_W 34816
#define QSM_TOT 69632

__global__ __launch_bounds__(256) void qkv_kernel(const float* __restrict__ x,
                                                  const float* __restrict__ w) {
    extern __shared__ char qsm[];
    const uint32_t sb = s2u(qsm);
    const int tid = threadIdx.x;
    const int wid = tid >> 5;
    const int lane = tid & 31;
    const int q4 = lane & 3;
    const int rr = lane >> 2;
    const int cb = blockIdx.x;    // segment: 0=Q 1=K 2=V
    const int mblk = blockIdx.y;  // row tile
    const int mw = (wid & 3) * 32;
    const int nw = (wid >> 2) * 64;

    const float4* Xf4 = reinterpret_cast<const float4*>(x) + (size_t)mblk * 128 * 32;
    const float4* Wf4 = reinterpret_cast<const float4*>(w);
#pragma unroll
    for (int i = 0; i < 16; i++) {
        int u = tid + 256 * i;
        int r = u >> 5, c4 = u & 31;
        float4 vx = Xf4[r * 32 + c4];
        uint2 px = {pkh2(vx.x, vx.y), pkh2(vx.z, vx.w)};
        *reinterpret_cast<uint2*>(qsm + QSM_X + r * 272 + c4 * 8) = px;
        float4 vw = Wf4[r * 96 + cb * 32 + c4];
        uint2 pw = {pkh2(vw.x, vw.y), pkh2(vw.z, vw.w)};
        *reinterpret_cast<uint2*>(qsm + QSM_W + r * 272 + c4 * 8) = pw;
    }
    __syncthreads();

    float c0[8][4], c1[8][4];
#pragma unroll
    for (int f = 0; f < 8; f++)
#pragma unroll
        for (int j = 0; j < 4; j++) {
            c0[f][j] = 0.f;
            c1[f][j] = 0.f;
        }

#pragma unroll
    for (int kc = 0; kc < 8; kc++) {
        uint32_t a0[4], a1[4];
        ldsm4(a0, sb + QSM_X + (mw + (lane & 15)) * 272 + kc * 32 + (lane >> 4) * 16);
        ldsm4(a1, sb + QSM_X + (mw + 16 + (lane & 15)) * 272 + kc * 32 + (lane >> 4) * 16);

        int krow = kc * 16 + ((lane >> 3) & 1) * 8 + (lane & 7);
        uint32_t baddr = sb + QSM_W + krow * 272 + nw * 2 + (lane >> 4) * 16;
        uint32_t b01[4], b23[4], b45[4], b67[4];
        ldsm4t(b01, baddr);
        ldsm4t(b23, baddr + 32);
        ldsm4t(b45, baddr + 64);
        ldsm4t(b67, baddr + 96);

        mma_f16(c0[0], a0, b01[0], b01[1]);
        mma_f16(c1[0], a1, b01[0], b01[1]);
        mma_f16(c0[1], a0, b01[2], b01[3]);
        mma_f16(c1[1], a1, b01[2], b01[3]);
        mma_f16(c0[2], a0, b23[0], b23[1]);
        mma_f16(c1[2], a1, b23[0], b23[1]);
        mma_f16(c0[3], a0, b23[2], b23[3]);
        mma_f16(c1[3], a1, b23[2], b23[3]);
        mma_f16(c0[4], a0, b45[0], b45[1]);
        mma_f16(c1[4], a1, b45[0], b45[1]);
        mma_f16(c0[5], a0, b45[2], b45[3]);
        mma_f16(c1[5], a1, b45[2], b45[3]);
        mma_f16(c0[6], a0, b67[0], b67[1]);
        mma_f16(c1[6], a1, b67[0], b67[1]);
        mma_f16(c0[7], a0, b67[2], b67[3]);
        mma_f16(c1[7], a1, b67[2], b67[3]);
    }

    const float kscale = 0.17677669529663688f * LOG2E;
    const float sc = (cb == 1) ? kscale : 1.f;
    __half* seg = (cb == 0) ? g_Q : (cb == 1) ? g_K : g_V;

#pragma unroll
    for (int f = 0; f < 8; f++) {
        int col = nw + 8 * f + 2 * q4;
        int hd = col >> 5, d = col & 31;
#pragma unroll
        for (int part = 0; part < 2; part++) {
            const float* cc = part ? c1[f] : c0[f];
            int mbase = mblk * 128 + mw + 16 * part + rr;
#pragma unroll
            for (int half = 0; half < 2; half++) {
                int m = mbase + 8 * half;
                int b = m >> 12, l = m & 4095;
                uint32_t pk = pkh2(cc[2 * half] * sc, cc[2 * half + 1] * sc);
                *reinterpret_cast<uint32_t*>(
                    seg + (((size_t)(b * NH + hd)) * LSEQ + l) * KD + d) = pk;
            }
        }
    }
}

// ---------------------------------------------------------------------------
// f16 HMMA flash attention, 512 threads = 16 warps.
// 6-buffer cp.async pipeline, one __syncthreads per 2 tiles; row-sums via
// extra HMMA with all-ones B fragment (no FADD/shfl reduction).
// ---------------------------------------------------------------------------
#define SMQ 0
#define SMK 10240                 /* 6 bufs x 10240 -> ends 71680 */
#define SMV 71680                 /* 6 bufs x 10240 -> ends 133120 */
#define SMBW 133120               /* f16 [128][72] = 18432 */
#define SMBH 151552               /* f32 [128][68] = 34816 */
#define SMTOT 186368
// overlays (consumed before K/V buffers first written)
#define SMPH 10240
#define SMPW 71680
#define SMRED 10240

__global__ __launch_bounds__(512, 1) void attn_kernel(const float* __restrict__ peh,
                                                      const float* __restrict__ pew,
                                                      float* __restrict__ out) {
    extern __shared__ char sm[];
    const uint32_t sb = s2u(sm);
    const int tid = threadIdx.x;
    const int wid = tid >> 5;
    const int lane = tid & 31;
    const int q4 = lane & 3;
    const int rr = lane >> 2;
    const int qb = blockIdx.x;    // 0..31
    const int bn = blockIdx.y;    // 0..7
    const int rw = wid & 7;
    const int h = wid >> 3;       // key-half
    const int m0 = rw * 16;

    const __half* Qg = g_Q + ((size_t)bn * LSEQ + (size_t)qb * 128) * KD;
    const __half* Kg = g_K + (size_t)bn * LSEQ * KD;
    const __half* Vg = g_V + (size_t)bn * LSEQ * KD;

    // ---- prologue: Q tile (f16, 80B rows) + pos tables (fp32, 144B rows) ----
    {
        int r = tid >> 2, c = tid & 3;
        CPA(sb + SMQ + r * 80 + c * 16, Qg + r * 32 + c * 8);
    }
    for (int u = tid; u < 1016; u += 512) {
        int r = u >> 3, c = u & 7;
        CPA(sb + SMPH + r * 144 + c * 16, peh + r * 32 + 4 * c);
        CPA(sb + SMPW + r * 144 + c * 16, pew + r * 32 + 4 * c);
    }
    CPC();
    CPW0();
    __syncthreads();

    // ---- bias precompute (x log2e): BW f16 [128][72], BH f32 [128][68] ----
    {
        int pair = tid >> 1, hc = tid & 1;
        int table = pair >> 7, qq = pair & 127;
        const __half2* qrow = reinterpret_cast<const __half2*>(sm + SMQ + qq * 80);
        float2 qv[16];
#pragma unroll
        for (int i = 0; i < 16; i++) qv[i] = __half22float2(qrow[i]);
        const float* tab = reinterpret_cast<const float*>(sm + (table ? SMPH : SMPW));
        int base = table ? (63 - 2 * qb - (qq >> 6)) : (63 - (qq & 63));
        __half* dstw = reinterpret_cast<__half*>(sm + SMBW) + qq * 72;
        float* dsth = reinterpret_cast<float*>(sm + SMBH) + qq * 68;
        for (int kc = 32 * hc; kc < 32 * hc + 32; kc++) {
            const float* er = tab + (base + kc) * 36;
            float s = 0.f;
#pragma unroll
            for (int i = 0; i < 8; i++) {
                float4 e = *reinterpret_cast<const float4*>(&er[4 * i]);
                s = fmaf(qv[2 * i].x, e.x, s);
                s = fmaf(qv[2 * i].y, e.y, s);
                s = fmaf(qv[2 * i + 1].x, e.z, s);
                s = fmaf(qv[2 * i + 1].y, e.w, s);
            }
            s *= LOG2E;
            if (table)
                dsth[kc] = s;
            else
                dstw[kc] = __float2half_rn(s);
        }
    }
    __syncthreads();

    // ---- Q A-fragments (m16k16 x2 chunks), fixed for all tiles ----
    uint32_t aQ[2][4];
#pragma unroll
    for (int kc = 0; kc < 2; kc++)
        ldsm4(aQ[kc], sb + SMQ + (m0 + (lane & 15)) * 80 + kc * 32 + (lane >> 4) * 16);

    const int ldr = tid >> 2, ldc = tid & 3;  // K/V load mapping
#define ISSUE_KV(t)                                                            \
    {                                                                          \
        const __half* Kt = Kg + (size_t)(t) * 128 * KD;                        \
        const __half* Vt = Vg + (size_t)(t) * 128 * KD;                        \
        uint32_t kd = sb + SMK + ((t) % 6) * 10240;                            \
        uint32_t vd = sb + SMV + ((t) % 6) * 10240;                            \
        CPA(kd + ldr * 80 + ldc * 16, Kt + ldr * 32 + ldc * 8);                \
        CPA(vd + ldr * 80 + ldc * 16, Vt + ldr * 32 + ldc * 8);                \
    }

    // warm up: pairs 0 and 1
    ISSUE_KV(0);
    ISSUE_KV(1);
    CPC();
    ISSUE_KV(2);
    ISSUE_KV(3);
    CPC();

    const __half2* BW2 = reinterpret_cast<const __half2*>(sm + SMBW);  // stride 36 h2
    const float* BHs = reinterpret_cast<const float*>(sm + SMBH);
    const uint32_t bOnes = 0x3C003C00u;

    float o[4][4];
#pragma unroll
    for (int i = 0; i < 4; i++)
#pragma unroll
        for (int j = 0; j < 4; j++) o[i][j] = 0.f;
    float sacc[4] = {0.f, 0.f, 0.f, 0.f};

    for (int p = 0; p < 16; p++) {
        if (p < 15) {
            CPW1();
        } else {
            CPW0();
        }
        __syncthreads();
        if (p + 2 < 16) {
            ISSUE_KV(2 * p + 4);
            ISSUE_KV(2 * p + 5);
            CPC();
        }

#pragma unroll
        for (int tt = 0; tt < 2; tt++) {
            const int t = 2 * p + tt;
            const uint32_t ksb = sb + SMK + (t % 6) * 10240;
            const uint32_t vsb = sb + SMV + (t % 6) * 10240;

            const float bh0 = BHs[(m0 + rr) * 68 + 2 * t + h];
            const float bh1 = BHs[(m0 + rr + 8) * 68 + 2 * t + h];

            // ---- S = bias + Q K^T ----
            float c[8][4];
#pragma unroll
            for (int nb = 0; nb < 8; nb++) {
                float2 w0 = __half22float2(BW2[(m0 + rr) * 36 + 4 * nb + q4]);
                float2 w1 = __half22float2(BW2[(m0 + rr + 8) * 36 + 4 * nb + q4]);
                c[nb][0] = w0.x + bh0;
                c[nb][1] = w0.y + bh0;
                c[nb][2] = w1.x + bh1;
                c[nb][3] = w1.y + bh1;
                uint32_t kb[4];
                ldsm4(kb, ksb + (64 * h + 8 * nb + (lane & 7)) * 80 + (lane >> 3) * 16);
                mma_f16(c[nb], aQ[0], kb[0], kb[1]);
                mma_f16(c[nb], aQ[1], kb[2], kb[3]);
            }

            // ---- P = 2^S ----
#pragma unroll
            for (int nb = 0; nb < 8; nb++) {
                c[nb][0] = ex2f(c[nb][0]);
                c[nb][1] = ex2f(c[nb][1]);
                c[nb][2] = ex2f(c[nb][2]);
                c[nb][3] = ex2f(c[nb][3]);
            }

            // ---- O += P V ; rowsum via ones-B mma ----
#pragma unroll
            for (int kc = 0; kc < 4; kc++) {
                uint32_t pa[4];
                pa[0] = pkh2(c[2 * kc][0], c[2 * kc][1]);
                pa[1] = pkh2(c[2 * kc][2], c[2 * kc][3]);
                pa[2] = pkh2(c[2 * kc + 1][0], c[2 * kc + 1][1]);
                pa[3] = pkh2(c[2 * kc + 1][2], c[2 * kc + 1][3]);

                int key = 64 * h + 16 * kc + ((lane >> 3) & 1) * 8 + (lane & 7);
                uint32_t a1 = vsb + key * 80 + (lane >> 4) * 16;
                uint32_t vb1[4], vb2[4];
                ldsm4t(vb1, a1);
                ldsm4t(vb2, a1 + 32);
                mma_f16(o[0], pa, vb1[0], vb1[1]);
                mma_f16(o[1], pa, vb1[2], vb1[3]);
                mma_f16(o[2], pa, vb2[0], vb2[1]);
                mma_f16(o[3], pa, vb2[2], vb2[3]);
                mma_f16(sacc, pa, bOnes, bOnes);
            }
        }
    }

    // ---- combine key-halves via smem (reuses K buffers) ----
    __syncthreads();
    if (h == 1) {
        float* red = reinterpret_cast<float*>(sm + SMRED) + ((size_t)(rw * 32 + lane)) * 20;
#pragma unroll
        for (int nb = 0; nb < 4; nb++)
#pragma unroll
            for (int j = 0; j < 4; j++) red[4 * nb + j] = o[nb][j];
        red[16] = sacc[0];
        red[17] = sacc[2];
    }
    __syncthreads();
    if (h == 0) {
        const float* red = reinterpret_cast<const float*>(sm + SMRED) + ((size_t)(rw * 32 + lane)) * 20;
#pragma unroll
        for (int nb = 0; nb < 4; nb++)
#pragma unroll
            for (int j = 0; j < 4; j++) o[nb][j] += red[4 * nb + j];
        const float inv0 = 1.f / (sacc[0] + red[16]);
        const float inv1 = 1.f / (sacc[2] + red[17]);

        const int b = bn >> 2, n = bn & 3;
        const int r0 = qb * 128 + m0 + rr;
        float* op0 = out + ((size_t)b * LSEQ + r0) * 128 + n * 32 + 2 * q4;
        float* op1 = op0 + 8 * 128;
#pragma unroll
        for (int nb = 0; nb < 4; nb++) {
            float2 v0, v1;
            v0.x = o[nb][0] * inv0;
            v0.y = o[nb][1] * inv0;
            v1.x = o[nb][2] * inv1;
            v1.y = o[nb][3] * inv1;
            *reinterpret_cast<float2*>(op0 + 8 * nb) = v0;
            *reinterpret_cast<float2*>(op1 + 8 * nb) = v1;
        }
    }
}

// ---------------------------------------------------------------------------
extern "C" void kernel_launch(void* const* d_in, const int* in_sizes, int n_in,
                              void* d_out, int out_size) {
    const float* x = (const float*)d_in[0];      // [2,64,64,128]
    const float* w = (const float*)d_in[1];      // [128,384]
    const float* peh = (const float*)d_in[2];    // [127,32]
    const float* pew = (const float*)d_in[3];    // [127,32]
    float* out = (float*)d_out;                  // [2,64,64,128] fp32

    cudaFuncSetAttribute(qkv_kernel, cudaFuncAttributeMaxDynamicSharedMemorySize,
                         QSM_TOT);
    cudaFuncSetAttribute(attn_kernel, cudaFuncAttributeMaxDynamicSharedMemorySize,
                         SMTOT);

    qkv_kernel<<<dim3(3, 64), 256, QSM_TOT>>>(x, w);
    attn_kernel<<<dim3(32, 8), 512, SMTOT>>>(peh, pew, out);
}

// round 14
// speedup vs baseline: 1.4699x; 1.0364x over previous
#include <cuda_runtime.h>
#include <cuda_fp16.h>
#include <cstdint>

#define NH 4
#define KD 32
#define LSEQ 4096
#define NT 32
#define LOG2E 1.4426950408889634f

// Scratch (allocation-free rule: __device__ globals)
__device__ __half g_Q[2 * NH * LSEQ * KD];  // f16 q
__device__ __half g_K[2 * NH * LSEQ * KD];  // f16 k * scale * log2e
__device__ __half g_V[2 * NH * LSEQ * KD];  // f16 v

// ---------------------------------------------------------------------------
// helpers
// ---------------------------------------------------------------------------
__device__ __forceinline__ uint32_t s2u(const void* p) {
    uint32_t a;
    asm("{ .reg .u64 t; cvta.to.shared.u64 t, %1; cvt.u32.u64 %0, t; }" : "=r"(a) : "l"(p));
    return a;
}
__device__ __forceinline__ uint32_t pkh2(float lo, float hi) {
    uint32_t d;
    asm("cvt.rn.f16x2.f32 %0, %1, %2;" : "=r"(d) : "f"(hi), "f"(lo));
    return d;
}
__device__ __forceinline__ uint32_t h2ex2(uint32_t x) {
    uint32_t y;
    asm("ex2.approx.f16x2 %0, %1;" : "=r"(y) : "r"(x));
    return y;
}
#define CPA(dst, src) asm volatile("cp.async.cg.shared.global [%0], [%1], 16;" ::"r"(dst), "l"(src))
#define CPC() asm volatile("cp.async.commit_group;" ::: "memory")
#define CPW0() asm volatile("cp.async.wait_group 0;" ::: "memory")
#define CPW1() asm volatile("cp.async.wait_group 1;" ::: "memory")

__device__ __forceinline__ void mma_f16(float* c, const uint32_t* a, uint32_t b0, uint32_t b1) {
    asm volatile(
        "mma.sync.aligned.m16n8k16.row.col.f32.f16.f16.f32 "
        "{%0,%1,%2,%3}, {%4,%5,%6,%7}, {%8,%9}, {%0,%1,%2,%3};"
        : "+f"(c[0]), "+f"(c[1]), "+f"(c[2]), "+f"(c[3])
        : "r"(a[0]), "r"(a[1]), "r"(a[2]), "r"(a[3]), "r"(b0), "r"(b1));
}
__device__ __forceinline__ void ldsm4(uint32_t* r, uint32_t addr) {
    asm volatile("ldmatrix.sync.aligned.m8n8.x4.shared.b16 {%0,%1,%2,%3}, [%4];"
                 : "=r"(r[0]), "=r"(r[1]), "=r"(r[2]), "=r"(r[3]) : "r"(addr));
}
__device__ __forceinline__ void ldsm4t(uint32_t* r, uint32_t addr) {
    asm volatile("ldmatrix.sync.aligned.m8n8.x4.trans.shared.b16 {%0,%1,%2,%3}, [%4];"
                 : "=r"(r[0]), "=r"(r[1]), "=r"(r[2]), "=r"(r[3]) : "r"(addr));
}

// ---------------------------------------------------------------------------
// QKV projection as f16 HMMA GEMM: C[8192,384] = X[8192,128] @ W[128,384].
// ---------------------------------------------------------------------------
#define QSM_X 0
#define QSM_W 34816
#define QSM_TOT 69632

__global__ __launch_bounds__(256) void qkv_kernel(const float* __restrict__ x,
                                                  const float* __restrict__ w) {
    extern __shared__ char qsm[];
    const uint32_t sb = s2u(qsm);
    const int tid = threadIdx.x;
    const int wid = tid >> 5;
    const int lane = tid & 31;
    const int q4 = lane & 3;
    const int rr = lane >> 2;
    const int cb = blockIdx.x;    // segment: 0=Q 1=K 2=V
    const int mblk = blockIdx.y;  // row tile
    const int mw = (wid & 3) * 32;
    const int nw = (wid >> 2) * 64;

    const float4* Xf4 = reinterpret_cast<const float4*>(x) + (size_t)mblk * 128 * 32;
    const float4* Wf4 = reinterpret_cast<const float4*>(w);
#pragma unroll
    for (int i = 0; i < 16; i++) {
        int u = tid + 256 * i;
        int r = u >> 5, c4 = u & 31;
        float4 vx = Xf4[r * 32 + c4];
        uint2 px = {pkh2(vx.y, vx.x), pkh2(vx.w, vx.z)};
        // NOTE: pkh2(lo,hi) packs (hi<<16)|lo with args (hi,lo) per asm order.
        px.x = pkh2(vx.x, vx.y);
        px.y = pkh2(vx.z, vx.w);
        *reinterpret_cast<uint2*>(qsm + QSM_X + r * 272 + c4 * 8) = px;
        float4 vw = Wf4[r * 96 + cb * 32 + c4];
        uint2 pw = {pkh2(vw.x, vw.y), pkh2(vw.z, vw.w)};
        *reinterpret_cast<uint2*>(qsm + QSM_W + r * 272 + c4 * 8) = pw;
    }
    __syncthreads();

    float c0[8][4], c1[8][4];
#pragma unroll
    for (int f = 0; f < 8; f++)
#pragma unroll
        for (int j = 0; j < 4; j++) {
            c0[f][j] = 0.f;
            c1[f][j] = 0.f;
        }

#pragma unroll
    for (int kc = 0; kc < 8; kc++) {
        uint32_t a0[4], a1[4];
        ldsm4(a0, sb + QSM_X + (mw + (lane & 15)) * 272 + kc * 32 + (lane >> 4) * 16);
        ldsm4(a1, sb + QSM_X + (mw + 16 + (lane & 15)) * 272 + kc * 32 + (lane >> 4) * 16);

        int krow = kc * 16 + ((lane >> 3) & 1) * 8 + (lane & 7);
        uint32_t baddr = sb + QSM_W + krow * 272 + nw * 2 + (lane >> 4) * 16;
        uint32_t b01[4], b23[4], b45[4], b67[4];
        ldsm4t(b01, baddr);
        ldsm4t(b23, baddr + 32);
        ldsm4t(b45, baddr + 64);
        ldsm4t(b67, baddr + 96);

        mma_f16(c0[0], a0, b01[0], b01[1]);
        mma_f16(c1[0], a1, b01[0], b01[1]);
        mma_f16(c0[1], a0, b01[2], b01[3]);
        mma_f16(c1[1], a1, b01[2], b01[3]);
        mma_f16(c0[2], a0, b23[0], b23[1]);
        mma_f16(c1[2], a1, b23[0], b23[1]);
        mma_f16(c0[3], a0, b23[2], b23[3]);
        mma_f16(c1[3], a1, b23[2], b23[3]);
        mma_f16(c0[4], a0, b45[0], b45[1]);
        mma_f16(c1[4], a1, b45[0], b45[1]);
        mma_f16(c0[5], a0, b45[2], b45[3]);
        mma_f16(c1[5], a1, b45[2], b45[3]);
        mma_f16(c0[6], a0, b67[0], b67[1]);
        mma_f16(c1[6], a1, b67[0], b67[1]);
        mma_f16(c0[7], a0, b67[2], b67[3]);
        mma_f16(c1[7], a1, b67[2], b67[3]);
    }

    const float kscale = 0.17677669529663688f * LOG2E;
    const float sc = (cb == 1) ? kscale : 1.f;
    __half* seg = (cb == 0) ? g_Q : (cb == 1) ? g_K : g_V;

#pragma unroll
    for (int f = 0; f < 8; f++) {
        int col = nw + 8 * f + 2 * q4;
        int hd = col >> 5, d = col & 31;
#pragma unroll
        for (int part = 0; part < 2; part++) {
            const float* cc = part ? c1[f] : c0[f];
            int mbase = mblk * 128 + mw + 16 * part + rr;
#pragma unroll
            for (int half = 0; half < 2; half++) {
                int m = mbase + 8 * half;
                int b = m >> 12, l = m & 4095;
                uint32_t pk = pkh2(cc[2 * half] * sc, cc[2 * half + 1] * sc);
                *reinterpret_cast<uint32_t*>(
                    seg + (((size_t)(b * NH + hd)) * LSEQ + l) * KD + d) = pk;
            }
        }
    }
}

// ---------------------------------------------------------------------------
// f16 HMMA flash attention, 512 threads = 16 warps.
// 6-buffer cp.async pipeline, sync per 2 tiles, rowsums via ones-B HMMA,
// softmax via pack-then-exp (ex2.approx.f16x2) — half the MUFU traffic.
// ---------------------------------------------------------------------------
#define SMQ 0
#define SMK 10240                 /* 6 bufs x 10240 -> ends 71680 */
#define SMV 71680                 /* 6 bufs x 10240 -> ends 133120 */
#define SMBW 133120               /* f16 [128][72] = 18432 */
#define SMBH 151552               /* f32 [128][68] = 34816 */
#define SMTOT 186368
// overlays (consumed before K/V buffers first written)
#define SMPH 10240
#define SMPW 71680
#define SMRED 10240

__global__ __launch_bounds__(512, 1) void attn_kernel(const float* __restrict__ peh,
                                                      const float* __restrict__ pew,
                                                      float* __restrict__ out) {
    extern __shared__ char sm[];
    const uint32_t sb = s2u(sm);
    const int tid = threadIdx.x;
    const int wid = tid >> 5;
    const int lane = tid & 31;
    const int q4 = lane & 3;
    const int rr = lane >> 2;
    const int qb = blockIdx.x;    // 0..31
    const int bn = blockIdx.y;    // 0..7
    const int rw = wid & 7;
    const int h = wid >> 3;       // key-half
    const int m0 = rw * 16;

    const __half* Qg = g_Q + ((size_t)bn * LSEQ + (size_t)qb * 128) * KD;
    const __half* Kg = g_K + (size_t)bn * LSEQ * KD;
    const __half* Vg = g_V + (size_t)bn * LSEQ * KD;

    // ---- prologue: Q tile (f16, 80B rows) + pos tables (fp32, 144B rows) ----
    {
        int r = tid >> 2, c = tid & 3;
        CPA(sb + SMQ + r * 80 + c * 16, Qg + r * 32 + c * 8);
    }
    for (int u = tid; u < 1016; u += 512) {
        int r = u >> 3, c = u & 7;
        CPA(sb + SMPH + r * 144 + c * 16, peh + r * 32 + 4 * c);
        CPA(sb + SMPW + r * 144 + c * 16, pew + r * 32 + 4 * c);
    }
    CPC();
    CPW0();
    __syncthreads();

    // ---- bias precompute (x log2e): BW f16 [128][72], BH f32 [128][68] ----
    {
        int pair = tid >> 1, hc = tid & 1;
        int table = pair >> 7, qq = pair & 127;
        const __half2* qrow = reinterpret_cast<const __half2*>(sm + SMQ + qq * 80);
        float2 qv[16];
#pragma unroll
        for (int i = 0; i < 16; i++) qv[i] = __half22float2(qrow[i]);
        const float* tab = reinterpret_cast<const float*>(sm + (table ? SMPH : SMPW));
        int base = table ? (63 - 2 * qb - (qq >> 6)) : (63 - (qq & 63));
        __half* dstw = reinterpret_cast<__half*>(sm + SMBW) + qq * 72;
        float* dsth = reinterpret_cast<float*>(sm + SMBH) + qq * 68;
        for (int kc = 32 * hc; kc < 32 * hc + 32; kc++) {
            const float* er = tab + (base + kc) * 36;
            float s = 0.f;
#pragma unroll
            for (int i = 0; i < 8; i++) {
                float4 e = *reinterpret_cast<const float4*>(&er[4 * i]);
                s = fmaf(qv[2 * i].x, e.x, s);
                s = fmaf(qv[2 * i].y, e.y, s);
                s = fmaf(qv[2 * i + 1].x, e.z, s);
                s = fmaf(qv[2 * i + 1].y, e.w, s);
            }
            s *= LOG2E;
            if (table)
                dsth[kc] = s;
            else
                dstw[kc] = __float2half_rn(s);
        }
    }
    __syncthreads();

    // ---- Q A-fragments (m16k16 x2 chunks), fixed for all tiles ----
    uint32_t aQ[2][4];
#pragma unroll
    for (int kc = 0; kc < 2; kc++)
        ldsm4(aQ[kc], sb + SMQ + (m0 + (lane & 15)) * 80 + kc * 32 + (lane >> 4) * 16);

    const int ldr = tid >> 2, ldc = tid & 3;  // K/V load mapping
#define ISSUE_KV(t)                                                            \
    {                                                                          \
        const __half* Kt = Kg + (size_t)(t) * 128 * KD;                        \
        const __half* Vt = Vg + (size_t)(t) * 128 * KD;                        \
        uint32_t kd = sb + SMK + ((t) % 6) * 10240;                            \
        uint32_t vd = sb + SMV + ((t) % 6) * 10240;                            \
        CPA(kd + ldr * 80 + ldc * 16, Kt + ldr * 32 + ldc * 8);                \
        CPA(vd + ldr * 80 + ldc * 16, Vt + ldr * 32 + ldc * 8);                \
    }

    // warm up: pairs 0 and 1
    ISSUE_KV(0);
    ISSUE_KV(1);
    CPC();
    ISSUE_KV(2);
    ISSUE_KV(3);
    CPC();

    const __half2* BW2 = reinterpret_cast<const __half2*>(sm + SMBW);  // stride 36 h2
    const float* BHs = reinterpret_cast<const float*>(sm + SMBH);
    const uint32_t bOnes = 0x3C003C00u;

    float o[4][4];
#pragma unroll
    for (int i = 0; i < 4; i++)
#pragma unroll
        for (int j = 0; j < 4; j++) o[i][j] = 0.f;
    float sacc[4] = {0.f, 0.f, 0.f, 0.f};

    for (int p = 0; p < 16; p++) {
        if (p < 15) {
            CPW1();
        } else {
            CPW0();
        }
        __syncthreads();
        if (p + 2 < 16) {
            ISSUE_KV(2 * p + 4);
            ISSUE_KV(2 * p + 5);
            CPC();
        }

#pragma unroll
        for (int tt = 0; tt < 2; tt++) {
            const int t = 2 * p + tt;
            const uint32_t ksb = sb + SMK + (t % 6) * 10240;
            const uint32_t vsb = sb + SMV + (t % 6) * 10240;

            const float bh0 = BHs[(m0 + rr) * 68 + 2 * t + h];
            const float bh1 = BHs[(m0 + rr + 8) * 68 + 2 * t + h];

            // ---- S = bias + Q K^T ----
            float c[8][4];
#pragma unroll
            for (int nb = 0; nb < 8; nb++) {
                float2 w0 = __half22float2(BW2[(m0 + rr) * 36 + 4 * nb + q4]);
                float2 w1 = __half22float2(BW2[(m0 + rr + 8) * 36 + 4 * nb + q4]);
                c[nb][0] = w0.x + bh0;
                c[nb][1] = w0.y + bh0;
                c[nb][2] = w1.x + bh1;
                c[nb][3] = w1.y + bh1;
                uint32_t kb[4];
                ldsm4(kb, ksb + (64 * h + 8 * nb + (lane & 7)) * 80 + (lane >> 3) * 16);
                mma_f16(c[nb], aQ[0], kb[0], kb[1]);
                mma_f16(c[nb], aQ[1], kb[2], kb[3]);
            }

            // ---- P = 2^S: pack-then-exp (f16x2 MUFU) ----
            uint32_t pex[8][2];
#pragma unroll
            for (int nb = 0; nb < 8; nb++) {
                pex[nb][0] = h2ex2(pkh2(c[nb][0], c[nb][1]));
                pex[nb][1] = h2ex2(pkh2(c[nb][2], c[nb][3]));
            }

            // ---- O += P V ; rowsum via ones-B mma ----
#pragma unroll
            for (int kc = 0; kc < 4; kc++) {
                uint32_t pa[4];
                pa[0] = pex[2 * kc][0];
                pa[1] = pex[2 * kc][1];
                pa[2] = pex[2 * kc + 1][0];
                pa[3] = pex[2 * kc + 1][1];

                int key = 64 * h + 16 * kc + ((lane >> 3) & 1) * 8 + (lane & 7);
                uint32_t a1 = vsb + key * 80 + (lane >> 4) * 16;
                uint32_t vb1[4], vb2[4];
                ldsm4t(vb1, a1);
                ldsm4t(vb2, a1 + 32);
                mma_f16(o[0], pa, vb1[0], vb1[1]);
                mma_f16(o[1], pa, vb1[2], vb1[3]);
                mma_f16(o[2], pa, vb2[0], vb2[1]);
                mma_f16(o[3], pa, vb2[2], vb2[3]);
                mma_f16(sacc, pa, bOnes, bOnes);
            }
        }
    }

    // ---- combine key-halves via smem (reuses K buffers) ----
    __syncthreads();
    if (h == 1) {
        float* red = reinterpret_cast<float*>(sm + SMRED) + ((size_t)(rw * 32 + lane)) * 20;
#pragma unroll
        for (int nb = 0; nb < 4; nb++)
#pragma unroll
            for (int j = 0; j < 4; j++) red[4 * nb + j] = o[nb][j];
        red[16] = sacc[0];
        red[17] = sacc[2];
    }
    __syncthreads();
    if (h == 0) {
        const float* red = reinterpret_cast<const float*>(sm + SMRED) + ((size_t)(rw * 32 + lane)) * 20;
#pragma unroll
        for (int nb = 0; nb < 4; nb++)
#pragma unroll
            for (int j = 0; j < 4; j++) o[nb][j] += red[4 * nb + j];
        const float inv0 = 1.f / (sacc[0] + red[16]);
        const float inv1 = 1.f / (sacc[2] + red[17]);

        const int b = bn >> 2, n = bn & 3;
        const int r0 = qb * 128 + m0 + rr;
        float* op0 = out + ((size_t)b * LSEQ + r0) * 128 + n * 32 + 2 * q4;
        float* op1 = op0 + 8 * 128;
#pragma unroll
        for (int nb = 0; nb < 4; nb++) {
            float2 v0, v1;
            v0.x = o[nb][0] * inv0;
            v0.y = o[nb][1] * inv0;
            v1.x = o[nb][2] * inv1;
            v1.y = o[nb][3] * inv1;
            *reinterpret_cast<float2*>(op0 + 8 * nb) = v0;
            *reinterpret_cast<float2*>(op1 + 8 * nb) = v1;
        }
    }
}

// ---------------------------------------------------------------------------
extern "C" void kernel_launch(void* const* d_in, const int* in_sizes, int n_in,
                              void* d_out, int out_size) {
    const float* x = (const float*)d_in[0];      // [2,64,64,128]
    const float* w = (const float*)d_in[1];      // [128,384]
    const float* peh = (const float*)d_in[2];    // [127,32]
    const float* pew = (const float*)d_in[3];    // [127,32]
    float* out = (float*)d_out;                  // [2,64,64,128] fp32

    cudaFuncSetAttribute(qkv_kernel, cudaFuncAttributeMaxDynamicSharedMemorySize,
                         QSM_TOT);
    cudaFuncSetAttribute(attn_kernel, cudaFuncAttributeMaxDynamicSharedMemorySize,
                         SMTOT);

    qkv_kernel<<<dim3(3, 64), 256, QSM_TOT>>>(x, w);
    attn_kernel<<<dim3(32, 8), 512, SMTOT>>>(peh, pew, out);
}

// round 15
// speedup vs baseline: 1.5282x; 1.0396x over previous
#include <cuda_runtime.h>
#include <cuda_fp16.h>
#include <cstdint>

#define NH 4
#define KD 32
#define LSEQ 4096
#define NT 32
#define LOG2E 1.4426950408889634f

// Scratch (allocation-free rule: __device__ globals)
__device__ __half g_Q[2 * NH * LSEQ * KD];  // f16 q
__device__ __half g_K[2 * NH * LSEQ * KD];  // f16 k * scale * log2e
__device__ __half g_V[2 * NH * LSEQ * KD];  // f16 v

// ---------------------------------------------------------------------------
// helpers
// ---------------------------------------------------------------------------
__device__ __forceinline__ uint32_t s2u(const void* p) {
    uint32_t a;
    asm("{ .reg .u64 t; cvta.to.shared.u64 t, %1; cvt.u32.u64 %0, t; }" : "=r"(a) : "l"(p));
    return a;
}
__device__ __forceinline__ uint32_t pkh2(float lo, float hi) {
    uint32_t d;
    asm("cvt.rn.f16x2.f32 %0, %1, %2;" : "=r"(d) : "f"(hi), "f"(lo));
    return d;
}
__device__ __forceinline__ uint32_t h2ex2(uint32_t x) {
    uint32_t y;
    asm("ex2.approx.f16x2 %0, %1;" : "=r"(y) : "r"(x));
    return y;
}
#define CPA(dst, src) asm volatile("cp.async.cg.shared.global [%0], [%1], 16;" ::"r"(dst), "l"(src))
#define CPC() asm volatile("cp.async.commit_group;" ::: "memory")
#define CPW0() asm volatile("cp.async.wait_group 0;" ::: "memory")
#define CPW1() asm volatile("cp.async.wait_group 1;" ::: "memory")
#define BARH(id) asm volatile("bar.sync %0, 256;" ::"r"(id) : "memory")

__device__ __forceinline__ void mma_f16(float* c, const uint32_t* a, uint32_t b0, uint32_t b1) {
    asm volatile(
        "mma.sync.aligned.m16n8k16.row.col.f32.f16.f16.f32 "
        "{%0,%1,%2,%3}, {%4,%5,%6,%7}, {%8,%9}, {%0,%1,%2,%3};"
        : "+f"(c[0]), "+f"(c[1]), "+f"(c[2]), "+f"(c[3])
        : "r"(a[0]), "r"(a[1]), "r"(a[2]), "r"(a[3]), "r"(b0), "r"(b1));
}
__device__ __forceinline__ void ldsm4(uint32_t* r, uint32_t addr) {
    asm volatile("ldmatrix.sync.aligned.m8n8.x4.shared.b16 {%0,%1,%2,%3}, [%4];"
                 : "=r"(r[0]), "=r"(r[1]), "=r"(r[2]), "=r"(r[3]) : "r"(addr));
}
__device__ __forceinline__ void ldsm4t(uint32_t* r, uint32_t addr) {
    asm volatile("ldmatrix.sync.aligned.m8n8.x4.trans.shared.b16 {%0,%1,%2,%3}, [%4];"
                 : "=r"(r[0]), "=r"(r[1]), "=r"(r[2]), "=r"(r[3]) : "r"(addr));
}

// ---------------------------------------------------------------------------
// QKV projection as f16 HMMA GEMM: C[8192,384] = X[8192,128] @ W[128,384].
// ---------------------------------------------------------------------------
#define QSM_X 0
#define QSM_W 34816
#define QSM_TOT 69632

__global__ __launch_bounds__(256) void qkv_kernel(const float* __restrict__ x,
                                                  const float* __restrict__ w) {
    extern __shared__ char qsm[];
    const uint32_t sb = s2u(qsm);
    const int tid = threadIdx.x;
    const int wid = tid >> 5;
    const int lane = tid & 31;
    const int q4 = lane & 3;
    const int rr = lane >> 2;
    const int cb = blockIdx.x;    // segment: 0=Q 1=K 2=V
    const int mblk = blockIdx.y;  // row tile
    const int mw = (wid & 3) * 32;
    const int nw = (wid >> 2) * 64;

    const float4* Xf4 = reinterpret_cast<const float4*>(x) + (size_t)mblk * 128 * 32;
    const float4* Wf4 = reinterpret_cast<const float4*>(w);
#pragma unroll
    for (int i = 0; i < 16; i++) {
        int u = tid + 256 * i;
        int r = u >> 5, c4 = u & 31;
        float4 vx = Xf4[r * 32 + c4];
        uint2 px = {pkh2(vx.x, vx.y), pkh2(vx.z, vx.w)};
        *reinterpret_cast<uint2*>(qsm + QSM_X + r * 272 + c4 * 8) = px;
        float4 vw = Wf4[r * 96 + cb * 32 + c4];
        uint2 pw = {pkh2(vw.x, vw.y), pkh2(vw.z, vw.w)};
        *reinterpret_cast<uint2*>(qsm + QSM_W + r * 272 + c4 * 8) = pw;
    }
    __syncthreads();

    float c0[8][4], c1[8][4];
#pragma unroll
    for (int f = 0; f < 8; f++)
#pragma unroll
        for (int j = 0; j < 4; j++) {
            c0[f][j] = 0.f;
            c1[f][j] = 0.f;
        }

#pragma unroll
    for (int kc = 0; kc < 8; kc++) {
        uint32_t a0[4], a1[4];
        ldsm4(a0, sb + QSM_X + (mw + (lane & 15)) * 272 + kc * 32 + (lane >> 4) * 16);
        ldsm4(a1, sb + QSM_X + (mw + 16 + (lane & 15)) * 272 + kc * 32 + (lane >> 4) * 16);

        int krow = kc * 16 + ((lane >> 3) & 1) * 8 + (lane & 7);
        uint32_t baddr = sb + QSM_W + krow * 272 + nw * 2 + (lane >> 4) * 16;
        uint32_t b01[4], b23[4], b45[4], b67[4];
        ldsm4t(b01, baddr);
        ldsm4t(b23, baddr + 32);
        ldsm4t(b45, baddr + 64);
        ldsm4t(b67, baddr + 96);

        mma_f16(c0[0], a0, b01[0], b01[1]);
        mma_f16(c1[0], a1, b01[0], b01[1]);
        mma_f16(c0[1], a0, b01[2], b01[3]);
        mma_f16(c1[1], a1, b01[2], b01[3]);
        mma_f16(c0[2], a0, b23[0], b23[1]);
        mma_f16(c1[2], a1, b23[0], b23[1]);
        mma_f16(c0[3], a0, b23[2], b23[3]);
        mma_f16(c1[3], a1, b23[2], b23[3]);
        mma_f16(c0[4], a0, b45[0], b45[1]);
        mma_f16(c1[4], a1, b45[0], b45[1]);
        mma_f16(c0[5], a0, b45[2], b45[3]);
        mma_f16(c1[5], a1, b45[2], b45[3]);
        mma_f16(c0[6], a0, b67[0], b67[1]);
        mma_f16(c1[6], a1, b67[0], b67[1]);
        mma_f16(c0[7], a0, b67[2], b67[3]);
        mma_f16(c1[7], a1, b67[2], b67[3]);
    }

    const float kscale = 0.17677669529663688f * LOG2E;
    const float sc = (cb == 1) ? kscale : 1.f;
    __half* seg = (cb == 0) ? g_Q : (cb == 1) ? g_K : g_V;

#pragma unroll
    for (int f = 0; f < 8; f++) {
        int col = nw + 8 * f + 2 * q4;
        int hd = col >> 5, d = col & 31;
#pragma unroll
        for (int part = 0; part < 2; part++) {
            const float* cc = part ? c1[f] : c0[f];
            int mbase = mblk * 128 + mw + 16 * part + rr;
#pragma unroll
            for (int half = 0; half < 2; half++) {
                int m = mbase + 8 * half;
                int b = m >> 12, l = m & 4095;
                uint32_t pk = pkh2(cc[2 * half] * sc, cc[2 * half + 1] * sc);
                *reinterpret_cast<uint32_t*>(
                    seg + (((size_t)(b * NH + hd)) * LSEQ + l) * KD + d) = pk;
            }
        }
    }
}

// ---------------------------------------------------------------------------
// f16 HMMA flash attention, 512 threads = 16 warps.
// Per-half named barriers (h=0 warps load+read rows 0-63, h=1 rows 64-127 —
// no cross-half smem hazard), 6-buffer cp.async pipeline, pair-interleaved
// software pipeline S(t0),exp(t0),S(t1),PV(t0),exp(t1),PV(t1).
// ---------------------------------------------------------------------------
#define SMQ 0
#define SMK 10240                 /* 6 bufs x 10240 -> ends 71680 */
#define SMV 71680                 /* 6 bufs x 10240 -> ends 133120 */
#define SMBW 133120               /* f16 [128][72] = 18432 */
#define SMBH 151552               /* f32 [128][68] = 34816 */
#define SMTOT 186368
// overlays (consumed before K/V buffers first written)
#define SMPH 10240
#define SMPW 71680
#define SMRED 10240

__global__ __launch_bounds__(512, 1) void attn_kernel(const float* __restrict__ peh,
                                                      const float* __restrict__ pew,
                                                      float* __restrict__ out) {
    extern __shared__ char sm[];
    const uint32_t sb = s2u(sm);
    const int tid = threadIdx.x;
    const int wid = tid >> 5;
    const int lane = tid & 31;
    const int q4 = lane & 3;
    const int rr = lane >> 2;
    const int qb = blockIdx.x;    // 0..31
    const int bn = blockIdx.y;    // 0..7
    const int rw = wid & 7;
    const int h = wid >> 3;       // key-half (tids [256h, 256h+256))
    const int m0 = rw * 16;

    const __half* Qg = g_Q + ((size_t)bn * LSEQ + (size_t)qb * 128) * KD;
    const __half* Kg = g_K + (size_t)bn * LSEQ * KD;
    const __half* Vg = g_V + (size_t)bn * LSEQ * KD;

    // ---- prologue: Q tile (f16, 80B rows) + pos tables (fp32, 144B rows) ----
    {
        int r = tid >> 2, c = tid & 3;
        CPA(sb + SMQ + r * 80 + c * 16, Qg + r * 32 + c * 8);
    }
    for (int u = tid; u < 1016; u += 512) {
        int r = u >> 3, c = u & 7;
        CPA(sb + SMPH + r * 144 + c * 16, peh + r * 32 + 4 * c);
        CPA(sb + SMPW + r * 144 + c * 16, pew + r * 32 + 4 * c);
    }
    CPC();
    CPW0();
    __syncthreads();

    // ---- bias precompute (x log2e): BW f16 [128][72], BH f32 [128][68] ----
    {
        int pair = tid >> 1, hc = tid & 1;
        int table = pair >> 7, qq = pair & 127;
        const __half2* qrow = reinterpret_cast<const __half2*>(sm + SMQ + qq * 80);
        float2 qv[16];
#pragma unroll
        for (int i = 0; i < 16; i++) qv[i] = __half22float2(qrow[i]);
        const float* tab = reinterpret_cast<const float*>(sm + (table ? SMPH : SMPW));
        int base = table ? (63 - 2 * qb - (qq >> 6)) : (63 - (qq & 63));
        __half* dstw = reinterpret_cast<__half*>(sm + SMBW) + qq * 72;
        float* dsth = reinterpret_cast<float*>(sm + SMBH) + qq * 68;
        for (int kc = 32 * hc; kc < 32 * hc + 32; kc++) {
            const float* er = tab + (base + kc) * 36;
            float s = 0.f;
#pragma unroll
            for (int i = 0; i < 8; i++) {
                float4 e = *reinterpret_cast<const float4*>(&er[4 * i]);
                s = fmaf(qv[2 * i].x, e.x, s);
                s = fmaf(qv[2 * i].y, e.y, s);
                s = fmaf(qv[2 * i + 1].x, e.z, s);
                s = fmaf(qv[2 * i + 1].y, e.w, s);
            }
            s *= LOG2E;
            if (table)
                dsth[kc] = s;
            else
                dstw[kc] = __float2half_rn(s);
        }
    }
    __syncthreads();

    // ---- Q A-fragments (m16k16 x2 chunks), fixed for all tiles ----
    uint32_t aQ[2][4];
#pragma unroll
    for (int kc = 0; kc < 2; kc++)
        ldsm4(aQ[kc], sb + SMQ + (m0 + (lane & 15)) * 80 + kc * 32 + (lane >> 4) * 16);

    const int ldr = tid >> 2, ldc = tid & 3;  // group h loads rows [64h,64h+64)
#define ISSUE_KV(t)                                                            \
    {                                                                          \
        const __half* Kt = Kg + (size_t)(t) * 128 * KD;                        \
        const __half* Vt = Vg + (size_t)(t) * 128 * KD;                        \
        uint32_t kd = sb + SMK + ((t) % 6) * 10240;                            \
        uint32_t vd = sb + SMV + ((t) % 6) * 10240;                            \
        CPA(kd + ldr * 80 + ldc * 16, Kt + ldr * 32 + ldc * 8);                \
        CPA(vd + ldr * 80 + ldc * 16, Vt + ldr * 32 + ldc * 8);                \
    }

    // warm up: pairs 0 and 1
    ISSUE_KV(0);
    ISSUE_KV(1);
    CPC();
    ISSUE_KV(2);
    ISSUE_KV(3);
    CPC();

    const __half2* BW2 = reinterpret_cast<const __half2*>(sm + SMBW);  // stride 36 h2
    const float* BHs = reinterpret_cast<const float*>(sm + SMBH);
    const uint32_t bOnes = 0x3C003C00u;

    float o[4][4];
#pragma unroll
    for (int i = 0; i < 4; i++)
#pragma unroll
        for (int j = 0; j < 4; j++) o[i][j] = 0.f;
    float sacc[4] = {0.f, 0.f, 0.f, 0.f};

    for (int p = 0; p < 16; p++) {
        if (p < 15) {
            CPW1();
        } else {
            CPW0();
        }
        BARH(1 + h);  // per-half barrier: halves are smem-disjoint in the loop
        if (p + 2 < 16) {
            ISSUE_KV(2 * p + 4);
            ISSUE_KV(2 * p + 5);
            CPC();
        }

        const int t0 = 2 * p, t1 = 2 * p + 1;
        const uint32_t ksb0 = sb + SMK + (t0 % 6) * 10240;
        const uint32_t vsb0 = sb + SMV + (t0 % 6) * 10240;
        const uint32_t ksb1 = sb + SMK + (t1 % 6) * 10240;
        const uint32_t vsb1 = sb + SMV + (t1 % 6) * 10240;

        float c[8][4];
        uint32_t pex[8][2];

        // ---- S(t0) = bias + Q K^T ----
        {
            const float bh0 = BHs[(m0 + rr) * 68 + 2 * t0 + h];
            const float bh1 = BHs[(m0 + rr + 8) * 68 + 2 * t0 + h];
#pragma unroll
            for (int nb = 0; nb < 8; nb++) {
                float2 w0 = __half22float2(BW2[(m0 + rr) * 36 + 4 * nb + q4]);
                float2 w1 = __half22float2(BW2[(m0 + rr + 8) * 36 + 4 * nb + q4]);
                c[nb][0] = w0.x + bh0;
                c[nb][1] = w0.y + bh0;
                c[nb][2] = w1.x + bh1;
                c[nb][3] = w1.y + bh1;
                uint32_t kb[4];
                ldsm4(kb, ksb0 + (64 * h + 8 * nb + (lane & 7)) * 80 + (lane >> 3) * 16);
                mma_f16(c[nb], aQ[0], kb[0], kb[1]);
                mma_f16(c[nb], aQ[1], kb[2], kb[3]);
            }
        }
        // ---- exp(t0) ----
#pragma unroll
        for (int nb = 0; nb < 8; nb++) {
            pex[nb][0] = h2ex2(pkh2(c[nb][0], c[nb][1]));
            pex[nb][1] = h2ex2(pkh2(c[nb][2], c[nb][3]));
        }
        // ---- S(t1) (independent of pex; fills PV(t0)/exp latency shadows) ----
        {
            const float bh0 = BHs[(m0 + rr) * 68 + 2 * t1 + h];
            const float bh1 = BHs[(m0 + rr + 8) * 68 + 2 * t1 + h];
#pragma unroll
            for (int nb = 0; nb < 8; nb++) {
                float2 w0 = __half22float2(BW2[(m0 + rr) * 36 + 4 * nb + q4]);
                float2 w1 = __half22float2(BW2[(m0 + rr + 8) * 36 + 4 * nb + q4]);
                float d0 = w0.x + bh0, d1 = w0.y + bh0;
                float d2 = w1.x + bh1, d3 = w1.y + bh1;
                uint32_t kb[4];
                ldsm4(kb, ksb1 + (64 * h + 8 * nb + (lane & 7)) * 80 + (lane >> 3) * 16);
                float cc[4] = {d0, d1, d2, d3};
                mma_f16(cc, aQ[0], kb[0], kb[1]);
                mma_f16(cc, aQ[1], kb[2], kb[3]);
                c[nb][0] = cc[0];
                c[nb][1] = cc[1];
                c[nb][2] = cc[2];
                c[nb][3] = cc[3];
            }
        }
        // ---- PV(t0) ----
#pragma unroll
        for (int kc = 0; kc < 4; kc++) {
            uint32_t pa[4];
            pa[0] = pex[2 * kc][0];
            pa[1] = pex[2 * kc][1];
            pa[2] = pex[2 * kc + 1][0];
            pa[3] = pex[2 * kc + 1][1];
            int key = 64 * h + 16 * kc + ((lane >> 3) & 1) * 8 + (lane & 7);
            uint32_t a1 = vsb0 + key * 80 + (lane >> 4) * 16;
            uint32_t vb1[4], vb2[4];
            ldsm4t(vb1, a1);
            ldsm4t(vb2, a1 + 32);
            mma_f16(o[0], pa, vb1[0], vb1[1]);
            mma_f16(o[1], pa, vb1[2], vb1[3]);
            mma_f16(o[2], pa, vb2[0], vb2[1]);
            mma_f16(o[3], pa, vb2[2], vb2[3]);
            mma_f16(sacc, pa, bOnes, bOnes);
        }
        // ---- exp(t1) ----
#pragma unroll
        for (int nb = 0; nb < 8; nb++) {
            pex[nb][0] = h2ex2(pkh2(c[nb][0], c[nb][1]));
            pex[nb][1] = h2ex2(pkh2(c[nb][2], c[nb][3]));
        }
        // ---- PV(t1) ----
#pragma unroll
        for (int kc = 0; kc < 4; kc++) {
            uint32_t pa[4];
            pa[0] = pex[2 * kc][0];
            pa[1] = pex[2 * kc][1];
            pa[2] = pex[2 * kc + 1][0];
            pa[3] = pex[2 * kc + 1][1];
            int key = 64 * h + 16 * kc + ((lane >> 3) & 1) * 8 + (lane & 7);
            uint32_t a1 = vsb1 + key * 80 + (lane >> 4) * 16;
            uint32_t vb1[4], vb2[4];
            ldsm4t(vb1, a1);
            ldsm4t(vb2, a1 + 32);
            mma_f16(o[0], pa, vb1[0], vb1[1]);
            mma_f16(o[1], pa, vb1[2], vb1[3]);
            mma_f16(o[2], pa, vb2[0], vb2[1]);
            mma_f16(o[3], pa, vb2[2], vb2[3]);
            mma_f16(sacc, pa, bOnes, bOnes);
        }
    }

    // ---- combine key-halves via smem (reuses K buffers) ----
    __syncthreads();
    if (h == 1) {
        float* red = reinterpret_cast<float*>(sm + SMRED) + ((size_t)(rw * 32 + lane)) * 20;
#pragma unroll
        for (int nb = 0; nb < 4; nb++)
#pragma unroll
            for (int j = 0; j < 4; j++) red[4 * nb + j] = o[nb][j];
        red[16] = sacc[0];
        red[17] = sacc[2];
    }
    __syncthreads();
    if (h == 0) {
        const float* red = reinterpret_cast<const float*>(sm + SMRED) + ((size_t)(rw * 32 + lane)) * 20;
#pragma unroll
        for (int nb = 0; nb < 4; nb++)
#pragma unroll
            for (int j = 0; j < 4; j++) o[nb][j] += red[4 * nb + j];
        const float inv0 = 1.f / (sacc[0] + red[16]);
        const float inv1 = 1.f / (sacc[2] + red[17]);

        const int b = bn >> 2, n = bn & 3;
        const int r0 = qb * 128 + m0 + rr;
        float* op0 = out + ((size_t)b * LSEQ + r0) * 128 + n * 32 + 2 * q4;
        float* op1 = op0 + 8 * 128;
#pragma unroll
        for (int nb = 0; nb < 4; nb++) {
            float2 v0, v1;
            v0.x = o[nb][0] * inv0;
            v0.y = o[nb][1] * inv0;
            v1.x = o[nb][2] * inv1;
            v1.y = o[nb][3] * inv1;
            *reinterpret_cast<float2*>(op0 + 8 * nb) = v0;
            *reinterpret_cast<float2*>(op1 + 8 * nb) = v1;
        }
    }
}

// ---------------------------------------------------------------------------
extern "C" void kernel_launch(void* const* d_in, const int* in_sizes, int n_in,
                              void* d_out, int out_size) {
    const float* x = (const float*)d_in[0];      // [2,64,64,128]
    const float* w = (const float*)d_in[1];      // [128,384]
    const float* peh = (const float*)d_in[2];    // [127,32]
    const float* pew = (const float*)d_in[3];    // [127,32]
    float* out = (float*)d_out;                  // [2,64,64,128] fp32

    cudaFuncSetAttribute(qkv_kernel, cudaFuncAttributeMaxDynamicSharedMemorySize,
                         QSM_TOT);
    cudaFuncSetAttribute(attn_kernel, cudaFuncAttributeMaxDynamicSharedMemorySize,
                         SMTOT);

    qkv_kernel<<<dim3(3, 64), 256, QSM_TOT>>>(x, w);
    attn_kernel<<<dim3(32, 8), 512, SMTOT>>>(peh, pew, out);
}